// round 1
// baseline (speedup 1.0000x reference)
#include <cuda_runtime.h>
#include <math.h>

// Problem constants
#define NB    4
#define NS    2048
#define NHID  2048
#define NDOWN 512
#define NUP   1024
#define NH    16
#define NROPE 64
#define NBS   (NB*NS)          // 8192 tokens

// ---------------- scratch (device globals; no runtime alloc allowed) ----------------
__device__ float g_ckv[NBS*NDOWN];
__device__ float g_cq [NBS*NDOWN];
__device__ float g_kc [NBS*NUP];
__device__ float g_vc [NBS*NUP];
__device__ float g_qc [NBS*NUP];
__device__ float g_qrr[NBS*NUP];
__device__ float g_kr [NBS*NROPE];
// Q/K packed per (b*H+h, 64-token tile) as [128 d][64 rows]  (pre-transposed for attention)
__device__ float g_Qt [NB*NH*NS*128];
__device__ float g_Kt [NB*NH*NS*128];
__device__ float g_ao [NBS*NUP];   // attention out in [B,S,H*64] layout

// ---------------- generic tiled SGEMM with bias: C[M,N] = A[M,K]@B[K,N] + bias ----------------
// 64x64 tile, 16x16 threads, 4x4 accum per thread. M%64==0, N%64==0, K%16==0 (all true here).
__global__ __launch_bounds__(256) void sgemm_bias(
    const float* __restrict__ A, const float* __restrict__ Bm,
    const float* __restrict__ bias, float* __restrict__ C,
    int M, int N, int K)
{
    __shared__ float As[16*68];   // [kk][row], padded stride 68 (16B-aligned, low conflicts)
    __shared__ float Bs[16*64];   // [kk][col]

    const int tx = threadIdx.x, ty = threadIdx.y;
    const int tid = ty*16 + tx;
    const int mBase = blockIdx.y*64, nBase = blockIdx.x*64;

    const int arow = tid >> 2;          // 0..63
    const int ak4  = (tid & 3) * 4;     // 0,4,8,12
    const int brow = tid >> 4;          // 0..15
    const int bcol = (tid & 15) * 4;    // 0..60

    const float* Ap = A + (size_t)(mBase + arow)*K + ak4;
    const float* Bp = Bm + (size_t)brow*N + nBase + bcol;

    float acc[4][4];
    #pragma unroll
    for (int i = 0; i < 4; i++)
        #pragma unroll
        for (int j = 0; j < 4; j++) acc[i][j] = 0.0f;

    for (int kt = 0; kt < K; kt += 16) {
        float4 av = *(const float4*)(Ap + kt);
        float4 bv = *(const float4*)(Bp + (size_t)kt*N);
        As[(ak4+0)*68 + arow] = av.x;
        As[(ak4+1)*68 + arow] = av.y;
        As[(ak4+2)*68 + arow] = av.z;
        As[(ak4+3)*68 + arow] = av.w;
        *(float4*)&Bs[brow*64 + bcol] = bv;
        __syncthreads();

        #pragma unroll
        for (int kk = 0; kk < 16; kk++) {
            float4 a = *(const float4*)&As[kk*68 + ty*4];
            float4 b = *(const float4*)&Bs[kk*64 + tx*4];
            float ar[4] = {a.x, a.y, a.z, a.w};
            float br[4] = {b.x, b.y, b.z, b.w};
            #pragma unroll
            for (int i = 0; i < 4; i++)
                #pragma unroll
                for (int j = 0; j < 4; j++)
                    acc[i][j] += ar[i] * br[j];
        }
        __syncthreads();
    }

    float4 bb = *(const float4*)&bias[nBase + tx*4];
    float bbr[4] = {bb.x, bb.y, bb.z, bb.w};
    #pragma unroll
    for (int i = 0; i < 4; i++) {
        float4 o;
        o.x = acc[i][0] + bbr[0];
        o.y = acc[i][1] + bbr[1];
        o.z = acc[i][2] + bbr[2];
        o.w = acc[i][3] + bbr[3];
        *(float4*)&C[(size_t)(mBase + ty*4 + i)*N + nBase + tx*4] = o;
    }
}

// ---------------- pack + RoPE: build Q/K in per-(bh,qtile) [128][64] transposed layout ----------
__global__ __launch_bounds__(256) void pack_qk(
    const float* __restrict__ kc, const float* __restrict__ qc,
    const float* __restrict__ qr, const float* __restrict__ kr,
    float* __restrict__ Qt, float* __restrict__ Kt)
{
    const int qt = blockIdx.x;   // 0..31
    const int bh = blockIdx.y;   // 0..63
    const int b  = bh >> 4, h = bh & 15;
    const int q0 = qt * 64;
    const int base = (bh*32 + qt) * (128*64);

    for (int it = 0; it < 32; it++) {
        int e = it*256 + threadIdx.x;   // 0..8191
        int d = e >> 6;                 // 0..127
        int r = e & 63;                 // token within tile
        int s = q0 + r;
        int row = b*NS + s;
        float kval, qval;
        if (d < 64) {
            kval = kc[(size_t)row*NUP + h*64 + d];
            qval = qc[(size_t)row*NUP + h*64 + d];
        } else {
            int dd = d - 64;
            int i2 = dd & ~1;           // paired index (2i)
            float fr = powf(10000.0f, -((float)i2) / 64.0f);
            float th = (float)s * fr;
            float cs, sn;
            sincosf(th, &sn, &cs);
            float kx1 = kr[(size_t)row*NROPE + i2];
            float kx2 = kr[(size_t)row*NROPE + i2 + 1];
            float qx1 = qr[(size_t)row*NUP + h*64 + i2];
            float qx2 = qr[(size_t)row*NUP + h*64 + i2 + 1];
            if (dd & 1) { kval = kx2*cs + kx1*sn; qval = qx2*cs + qx1*sn; }
            else        { kval = kx1*cs - kx2*sn; qval = qx1*cs - qx2*sn; }
        }
        Kt[base + e] = kval;
        Qt[base + e] = qval;
    }
}

// ---------------- causal flash attention: 64 q-rows per CTA, d=128, dv=64 ----------------
__global__ __launch_bounds__(256) void attn_kernel(
    const float* __restrict__ Qt, const float* __restrict__ Kt,
    const float* __restrict__ V, float* __restrict__ O)
{
    extern __shared__ float sm[];
    float* Qs = sm;            // [128][64] = 8192
    float* Ks = sm + 8192;     // [128][64] = 8192
    float* Vs = sm + 16384;    // [64][64]  = 4096
    float* Ps = sm + 20480;    // [64][65]  = 4160 (padded, scalar access)

    const float SCALEF = 0.051776695296636886f;  // 1/(sqrt(128)+sqrt(64))
    const int tx = threadIdx.x, ty = threadIdx.y;
    const int tid = ty*16 + tx;
    const int qt = blockIdx.x, bh = blockIdx.y;
    const int b = bh >> 4, h = bh & 15;
    const int q0 = qt * 64;

    // load Q tile (already transposed in gmem -> contiguous copy)
    const float* Qg = Qt + (size_t)(bh*32 + qt) * 8192;
    #pragma unroll
    for (int it = 0; it < 8; it++)
        *(float4*)&Qs[(it*256 + tid)*4] = *(const float4*)&Qg[(it*256 + tid)*4];

    float m[4], l[4], acc2[4][4];
    #pragma unroll
    for (int i = 0; i < 4; i++) {
        m[i] = -1e30f; l[i] = 0.0f;
        #pragma unroll
        for (int j = 0; j < 4; j++) acc2[i][j] = 0.0f;
    }

    for (int kt = 0; kt <= qt; kt++) {
        __syncthreads();   // prior PV done before overwriting Ks/Vs (covers Q readiness too)
        const float* Kg = Kt + (size_t)(bh*32 + kt) * 8192;
        #pragma unroll
        for (int it = 0; it < 8; it++)
            *(float4*)&Ks[(it*256 + tid)*4] = *(const float4*)&Kg[(it*256 + tid)*4];
        const float* Vg = V + (size_t)(b*NS + kt*64)*NUP + h*64;
        #pragma unroll
        for (int it = 0; it < 4; it++) {
            int e = it*256 + tid;                  // 0..1023
            int key = e >> 4, d0 = (e & 15)*4;
            *(float4*)&Vs[key*64 + d0] = *(const float4*)&Vg[(size_t)key*NUP + d0];
        }
        __syncthreads();

        // scores: 64x64 via outer product over 128 dims
        float acc[4][4];
        #pragma unroll
        for (int i = 0; i < 4; i++)
            #pragma unroll
            for (int j = 0; j < 4; j++) acc[i][j] = 0.0f;

        #pragma unroll 4
        for (int dk = 0; dk < 128; dk++) {
            float4 a = *(const float4*)&Qs[dk*64 + ty*4];
            float4 c = *(const float4*)&Ks[dk*64 + tx*4];
            float ar[4] = {a.x, a.y, a.z, a.w};
            float cr[4] = {c.x, c.y, c.z, c.w};
            #pragma unroll
            for (int i = 0; i < 4; i++)
                #pragma unroll
                for (int j = 0; j < 4; j++)
                    acc[i][j] += ar[i] * cr[j];
        }

        const int k0 = kt * 64;
        const bool diag = (kt == qt);
        #pragma unroll
        for (int i = 0; i < 4; i++) {
            int qrow = q0 + ty*4 + i;
            float s[4];
            #pragma unroll
            for (int j = 0; j < 4; j++) {
                float sv = acc[i][j] * SCALEF;
                if (diag && (k0 + tx*4 + j > qrow)) sv = -1e9f;
                s[j] = sv;
            }
            float mx = fmaxf(fmaxf(s[0], s[1]), fmaxf(s[2], s[3]));
            mx = fmaxf(mx, __shfl_xor_sync(0xffffffffu, mx, 1));
            mx = fmaxf(mx, __shfl_xor_sync(0xffffffffu, mx, 2));
            mx = fmaxf(mx, __shfl_xor_sync(0xffffffffu, mx, 4));
            mx = fmaxf(mx, __shfl_xor_sync(0xffffffffu, mx, 8));
            float mnew = fmaxf(m[i], mx);
            float corr = __expf(m[i] - mnew);
            float p[4], ps = 0.0f;
            #pragma unroll
            for (int j = 0; j < 4; j++) { p[j] = __expf(s[j] - mnew); ps += p[j]; }
            ps += __shfl_xor_sync(0xffffffffu, ps, 1);
            ps += __shfl_xor_sync(0xffffffffu, ps, 2);
            ps += __shfl_xor_sync(0xffffffffu, ps, 4);
            ps += __shfl_xor_sync(0xffffffffu, ps, 8);
            l[i] = l[i]*corr + ps;
            m[i] = mnew;
            #pragma unroll
            for (int j = 0; j < 4; j++) acc2[i][j] *= corr;
            #pragma unroll
            for (int j = 0; j < 4; j++)
                Ps[(tx*4 + j)*65 + ty*4 + i] = p[j];
        }
        __syncthreads();

        // O += P @ V
        #pragma unroll 8
        for (int k = 0; k < 64; k++) {
            float4 v = *(const float4*)&Vs[k*64 + tx*4];
            #pragma unroll
            for (int i = 0; i < 4; i++) {
                float a = Ps[k*65 + ty*4 + i];
                acc2[i][0] += a * v.x;
                acc2[i][1] += a * v.y;
                acc2[i][2] += a * v.z;
                acc2[i][3] += a * v.w;
            }
        }
    }

    #pragma unroll
    for (int i = 0; i < 4; i++) {
        float inv = 1.0f / l[i];
        int qrow = q0 + ty*4 + i;
        float4 o;
        o.x = acc2[i][0]*inv; o.y = acc2[i][1]*inv;
        o.z = acc2[i][2]*inv; o.w = acc2[i][3]*inv;
        *(float4*)&O[(size_t)(b*NS + qrow)*NUP + h*64 + tx*4] = o;
    }
}

// ---------------- host launcher ----------------
extern "C" void kernel_launch(void* const* d_in, const int* in_sizes, int n_in,
                              void* d_out, int out_size)
{
    (void)in_sizes; (void)n_in; (void)out_size;
    const float* X     = (const float*)d_in[0];
    // d_in[1] = mask (causal tril, handled analytically)
    const float* W_dkv = (const float*)d_in[2];
    const float* b_dkv = (const float*)d_in[3];
    const float* W_dq  = (const float*)d_in[4];
    const float* b_dq  = (const float*)d_in[5];
    const float* W_uk  = (const float*)d_in[6];
    const float* b_uk  = (const float*)d_in[7];
    const float* W_uv  = (const float*)d_in[8];
    const float* b_uv  = (const float*)d_in[9];
    const float* W_uq  = (const float*)d_in[10];
    const float* b_uq  = (const float*)d_in[11];
    const float* W_qr  = (const float*)d_in[12];
    const float* b_qr  = (const float*)d_in[13];
    const float* W_kr  = (const float*)d_in[14];
    const float* b_kr  = (const float*)d_in[15];
    const float* W_fc  = (const float*)d_in[16];
    const float* b_fc  = (const float*)d_in[17];
    float* out = (float*)d_out;

    float *ckv, *cq, *kc, *vc, *qc, *qrr, *kr, *Qt, *Kt, *ao;
    cudaGetSymbolAddress((void**)&ckv, g_ckv);
    cudaGetSymbolAddress((void**)&cq,  g_cq);
    cudaGetSymbolAddress((void**)&kc,  g_kc);
    cudaGetSymbolAddress((void**)&vc,  g_vc);
    cudaGetSymbolAddress((void**)&qc,  g_qc);
    cudaGetSymbolAddress((void**)&qrr, g_qrr);
    cudaGetSymbolAddress((void**)&kr,  g_kr);
    cudaGetSymbolAddress((void**)&Qt,  g_Qt);
    cudaGetSymbolAddress((void**)&Kt,  g_Kt);
    cudaGetSymbolAddress((void**)&ao,  g_ao);

    dim3 blk(16, 16);

    // down projections + rope-k raw
    sgemm_bias<<<dim3(NDOWN/64, NBS/64), blk>>>(X, W_dkv, b_dkv, ckv, NBS, NDOWN, NHID);
    sgemm_bias<<<dim3(NDOWN/64, NBS/64), blk>>>(X, W_dq,  b_dq,  cq,  NBS, NDOWN, NHID);
    sgemm_bias<<<dim3(NROPE/64, NBS/64), blk>>>(X, W_kr,  b_kr,  kr,  NBS, NROPE, NHID);
    // up projections
    sgemm_bias<<<dim3(NUP/64, NBS/64), blk>>>(ckv, W_uk, b_uk, kc,  NBS, NUP, NDOWN);
    sgemm_bias<<<dim3(NUP/64, NBS/64), blk>>>(ckv, W_uv, b_uv, vc,  NBS, NUP, NDOWN);
    sgemm_bias<<<dim3(NUP/64, NBS/64), blk>>>(cq,  W_uq, b_uq, qc,  NBS, NUP, NDOWN);
    sgemm_bias<<<dim3(NUP/64, NBS/64), blk>>>(cq,  W_qr, b_qr, qrr, NBS, NUP, NDOWN);
    // rope + pack into transposed per-tile layout
    pack_qk<<<dim3(32, 64), 256>>>(kc, qc, qrr, kr, Qt, Kt);
    // causal flash attention
    const int SMEM = (8192 + 8192 + 4096 + 64*65) * 4;  // 98560 bytes
    cudaFuncSetAttribute(attn_kernel, cudaFuncAttributeMaxDynamicSharedMemorySize, SMEM);
    attn_kernel<<<dim3(32, 64), blk, SMEM>>>(Qt, Kt, vc, ao);
    // final projection
    sgemm_bias<<<dim3(NHID/64, NBS/64), blk>>>(ao, W_fc, b_fc, out, NBS, NHID, NUP);
}

// round 3
// speedup vs baseline: 1.6480x; 1.6480x over previous
#include <cuda_runtime.h>
#include <math.h>
#include <stdint.h>

// Problem constants
#define NB    4
#define NS    2048
#define NHID  2048
#define NDOWN 512
#define NUP   1024
#define NH    16
#define NROPE 64
#define NBS   (NB*NS)          // 8192 tokens

// ---------------- scratch (device globals; no runtime alloc allowed) ----------------
__device__ float g_ckv[NBS*NDOWN];
__device__ float g_cq [NBS*NDOWN];
__device__ float g_kc [NBS*NUP];
__device__ float g_vc [NBS*NUP];
__device__ float g_qc [NBS*NUP];
__device__ float g_qrr[NBS*NUP];
__device__ float g_kr [NBS*NROPE];
__device__ float g_Qt [NB*NH*NS*128];
__device__ float g_Kt [NB*NH*NS*128];
__device__ float g_ao [NBS*NUP];

// transposed weights [N,K]
__device__ float g_Wt_dkv[NDOWN*NHID];
__device__ float g_Wt_dq [NDOWN*NHID];
__device__ float g_Wt_uk [NUP*NDOWN];
__device__ float g_Wt_uv [NUP*NDOWN];
__device__ float g_Wt_uq [NUP*NDOWN];
__device__ float g_Wt_qr [NUP*NDOWN];
__device__ float g_Wt_fc [NHID*NUP];

// ---------------- helpers ----------------
__device__ __forceinline__ uint32_t tf32r(float x) {
    uint32_t u;
    asm("cvt.rna.tf32.f32 %0, %1;" : "=r"(u) : "f"(x));
    return u;
}
__device__ __forceinline__ void mma_tf32_16n8k8(
    float& c0, float& c1, float& c2, float& c3,
    uint32_t a0, uint32_t a1, uint32_t a2, uint32_t a3,
    uint32_t b0, uint32_t b1)
{
    asm volatile(
        "mma.sync.aligned.m16n8k8.row.col.f32.tf32.tf32.f32 "
        "{%0,%1,%2,%3}, {%4,%5,%6,%7}, {%8,%9}, {%0,%1,%2,%3};"
        : "+f"(c0), "+f"(c1), "+f"(c2), "+f"(c3)
        : "r"(a0), "r"(a1), "r"(a2), "r"(a3), "r"(b0), "r"(b1));
}

// ---------------- weight transpose: Wt[n*K+k] = W[k*N+n] ----------------
__global__ __launch_bounds__(256) void transpose_k(
    const float* __restrict__ W, float* __restrict__ Wt, int K, int N)
{
    __shared__ float t[32][33];
    int n0 = blockIdx.x * 32, k0 = blockIdx.y * 32;
    int tx = threadIdx.x, ty = threadIdx.y;
    #pragma unroll
    for (int i = ty; i < 32; i += 8)
        t[i][tx] = W[(size_t)(k0 + i) * N + n0 + tx];
    __syncthreads();
    #pragma unroll
    for (int i = ty; i < 32; i += 8)
        Wt[(size_t)(n0 + i) * K + k0 + tx] = t[tx][i];
}

// ---------------- tf32 mma.sync GEMM: C[M,N] = A[M,K] @ Wt[N,K]^T + bias ------------
// 128x128 CTA tile, BK=32, 8 warps each 64x32. M%128==0, N%128==0, K%32==0.
#define STRD 36
#define BUFSZ (128*STRD)
__global__ __launch_bounds__(256) void mma_gemm(
    const float* __restrict__ A, const float* __restrict__ Wt,
    const float* __restrict__ bias, float* __restrict__ C,
    int N, int K)
{
    extern __shared__ float sm[];
    float* As = sm;             // [2][128][STRD]
    float* Bs = sm + 2*BUFSZ;   // [2][128][STRD]

    const int tid = threadIdx.x;
    const int w = tid >> 5, lane = tid & 31;
    const int g = lane >> 2, tig = lane & 3;
    const int wm = (w & 1) * 64;       // warp row base within tile
    const int wn = (w >> 1) * 32;      // warp col base within tile
    const int M0 = blockIdx.y * 128, N0 = blockIdx.x * 128;

    const float* Ag = A  + (size_t)M0 * K;
    const float* Bg = Wt + (size_t)N0 * K;

    float acc[4][4][4];
    #pragma unroll
    for (int mt = 0; mt < 4; mt++)
        #pragma unroll
        for (int nt = 0; nt < 4; nt++)
            #pragma unroll
            for (int q = 0; q < 4; q++) acc[mt][nt][q] = 0.0f;

    const int row_ld = tid >> 3;          // 0..31 step over 128 rows in 4 its
    const int kc_ld  = (tid & 7) * 4;     // 0..28

    // ---- load chunk 0 into buffer 0 ----
    {
        #pragma unroll
        for (int it = 0; it < 4; it++) {
            int row = it * 32 + row_ld;
            float4 va = *(const float4*)(Ag + (size_t)row * K + kc_ld);
            float4 vb = *(const float4*)(Bg + (size_t)row * K + kc_ld);
            float* da = As + row * STRD + kc_ld;
            float* db = Bs + row * STRD + kc_ld;
            da[0] = __uint_as_float(tf32r(va.x));
            da[1] = __uint_as_float(tf32r(va.y));
            da[2] = __uint_as_float(tf32r(va.z));
            da[3] = __uint_as_float(tf32r(va.w));
            db[0] = __uint_as_float(tf32r(vb.x));
            db[1] = __uint_as_float(tf32r(vb.y));
            db[2] = __uint_as_float(tf32r(vb.z));
            db[3] = __uint_as_float(tf32r(vb.w));
        }
    }
    __syncthreads();

    const int NC = K >> 5;
    for (int ch = 0; ch < NC; ch++) {
        const int buf = ch & 1;
        const float* Ab = As + buf * BUFSZ;
        const float* Bb = Bs + buf * BUFSZ;

        // prefetch next chunk to registers
        float4 ra[4], rb[4];
        const bool more = (ch + 1 < NC);
        if (more) {
            const int kc0 = (ch + 1) * 32;
            #pragma unroll
            for (int it = 0; it < 4; it++) {
                int row = it * 32 + row_ld;
                ra[it] = *(const float4*)(Ag + (size_t)row * K + kc0 + kc_ld);
                rb[it] = *(const float4*)(Bg + (size_t)row * K + kc0 + kc_ld);
            }
        }

        // compute on current buffer: 4 k-steps of 8
        #pragma unroll
        for (int ks = 0; ks < 4; ks++) {
            const int k0 = ks * 8;
            uint32_t af[4][4], bf[4][2];
            #pragma unroll
            for (int mt = 0; mt < 4; mt++) {
                const float* p = Ab + (wm + mt * 16 + g) * STRD + k0 + tig;
                af[mt][0] = __float_as_uint(p[0]);
                af[mt][1] = __float_as_uint(p[8 * STRD]);
                af[mt][2] = __float_as_uint(p[4]);
                af[mt][3] = __float_as_uint(p[8 * STRD + 4]);
            }
            #pragma unroll
            for (int nt = 0; nt < 4; nt++) {
                const float* p = Bb + (wn + nt * 8 + g) * STRD + k0 + tig;
                bf[nt][0] = __float_as_uint(p[0]);
                bf[nt][1] = __float_as_uint(p[4]);
            }
            #pragma unroll
            for (int mt = 0; mt < 4; mt++)
                #pragma unroll
                for (int nt = 0; nt < 4; nt++)
                    mma_tf32_16n8k8(acc[mt][nt][0], acc[mt][nt][1],
                                    acc[mt][nt][2], acc[mt][nt][3],
                                    af[mt][0], af[mt][1], af[mt][2], af[mt][3],
                                    bf[nt][0], bf[nt][1]);
        }

        if (more) {
            float* da0 = As + (buf ^ 1) * BUFSZ;
            float* db0 = Bs + (buf ^ 1) * BUFSZ;
            #pragma unroll
            for (int it = 0; it < 4; it++) {
                int row = it * 32 + row_ld;
                float* da = da0 + row * STRD + kc_ld;
                float* db = db0 + row * STRD + kc_ld;
                da[0] = __uint_as_float(tf32r(ra[it].x));
                da[1] = __uint_as_float(tf32r(ra[it].y));
                da[2] = __uint_as_float(tf32r(ra[it].z));
                da[3] = __uint_as_float(tf32r(ra[it].w));
                db[0] = __uint_as_float(tf32r(rb[it].x));
                db[1] = __uint_as_float(tf32r(rb[it].y));
                db[2] = __uint_as_float(tf32r(rb[it].z));
                db[3] = __uint_as_float(tf32r(rb[it].w));
            }
        }
        __syncthreads();
    }

    // epilogue: c0 at (row+g, col+2*tig), c1 col+1, c2/c3 row+8
    #pragma unroll
    for (int mt = 0; mt < 4; mt++) {
        const int row = M0 + wm + mt * 16 + g;
        #pragma unroll
        for (int nt = 0; nt < 4; nt++) {
            const int col = N0 + wn + nt * 8 + 2 * tig;
            float b0 = bias[col], b1 = bias[col + 1];
            float2 o0; o0.x = acc[mt][nt][0] + b0; o0.y = acc[mt][nt][1] + b1;
            float2 o1; o1.x = acc[mt][nt][2] + b0; o1.y = acc[mt][nt][3] + b1;
            *(float2*)(C + (size_t)row * N + col)       = o0;
            *(float2*)(C + (size_t)(row + 8) * N + col) = o1;
        }
    }
}

// ---------------- fp32 SGEMM (kept for the small W_kr projection) ----------------
__global__ __launch_bounds__(256) void sgemm_bias(
    const float* __restrict__ A, const float* __restrict__ Bm,
    const float* __restrict__ bias, float* __restrict__ C,
    int M, int N, int K)
{
    __shared__ float Ash[16*68];
    __shared__ float Bsh[16*64];

    const int tx = threadIdx.x, ty = threadIdx.y;
    const int tid = ty*16 + tx;
    const int mBase = blockIdx.y*64, nBase = blockIdx.x*64;

    const int arow = tid >> 2;
    const int ak4  = (tid & 3) * 4;
    const int brow = tid >> 4;
    const int bcol = (tid & 15) * 4;

    const float* Ap = A + (size_t)(mBase + arow)*K + ak4;
    const float* Bp = Bm + (size_t)brow*N + nBase + bcol;

    float acc[4][4];
    #pragma unroll
    for (int i = 0; i < 4; i++)
        #pragma unroll
        for (int j = 0; j < 4; j++) acc[i][j] = 0.0f;

    for (int kt = 0; kt < K; kt += 16) {
        float4 av = *(const float4*)(Ap + kt);
        float4 bv = *(const float4*)(Bp + (size_t)kt*N);
        Ash[(ak4+0)*68 + arow] = av.x;
        Ash[(ak4+1)*68 + arow] = av.y;
        Ash[(ak4+2)*68 + arow] = av.z;
        Ash[(ak4+3)*68 + arow] = av.w;
        *(float4*)&Bsh[brow*64 + bcol] = bv;
        __syncthreads();

        #pragma unroll
        for (int kk = 0; kk < 16; kk++) {
            float4 a = *(const float4*)&Ash[kk*68 + ty*4];
            float4 b = *(const float4*)&Bsh[kk*64 + tx*4];
            float ar[4] = {a.x, a.y, a.z, a.w};
            float br[4] = {b.x, b.y, b.z, b.w};
            #pragma unroll
            for (int i = 0; i < 4; i++)
                #pragma unroll
                for (int j = 0; j < 4; j++)
                    acc[i][j] += ar[i] * br[j];
        }
        __syncthreads();
    }

    float4 bb = *(const float4*)&bias[nBase + tx*4];
    float bbr[4] = {bb.x, bb.y, bb.z, bb.w};
    #pragma unroll
    for (int i = 0; i < 4; i++) {
        float4 o;
        o.x = acc[i][0] + bbr[0];
        o.y = acc[i][1] + bbr[1];
        o.z = acc[i][2] + bbr[2];
        o.w = acc[i][3] + bbr[3];
        *(float4*)&C[(size_t)(mBase + ty*4 + i)*N + nBase + tx*4] = o;
    }
}

// ---------------- pack + RoPE: build Q/K in per-(bh,qtile) [128][64] transposed layout ----------
__global__ __launch_bounds__(256) void pack_qk(
    const float* __restrict__ kc, const float* __restrict__ qc,
    const float* __restrict__ qr, const float* __restrict__ kr,
    float* __restrict__ Qt, float* __restrict__ Kt)
{
    const int qt = blockIdx.x;
    const int bh = blockIdx.y;
    const int b  = bh >> 4, h = bh & 15;
    const int q0 = qt * 64;
    const int base = (bh*32 + qt) * (128*64);

    for (int it = 0; it < 32; it++) {
        int e = it*256 + threadIdx.x;
        int d = e >> 6;
        int rr = e & 63;
        int s = q0 + rr;
        int row = b*NS + s;
        float kval, qval;
        if (d < 64) {
            kval = kc[(size_t)row*NUP + h*64 + d];
            qval = qc[(size_t)row*NUP + h*64 + d];
        } else {
            int dd = d - 64;
            int i2 = dd & ~1;
            float fr = powf(10000.0f, -((float)i2) / 64.0f);
            float th = (float)s * fr;
            float cs, sn;
            sincosf(th, &sn, &cs);
            float kx1 = kr[(size_t)row*NROPE + i2];
            float kx2 = kr[(size_t)row*NROPE + i2 + 1];
            float qx1 = qr[(size_t)row*NUP + h*64 + i2];
            float qx2 = qr[(size_t)row*NUP + h*64 + i2 + 1];
            if (dd & 1) { kval = kx2*cs + kx1*sn; qval = qx2*cs + qx1*sn; }
            else        { kval = kx1*cs - kx2*sn; qval = qx1*cs - qx2*sn; }
        }
        Kt[base + e] = kval;
        Qt[base + e] = qval;
    }
}

// ---------------- causal flash attention: 64 q-rows per CTA, d=128, dv=64 ----------------
__global__ __launch_bounds__(256) void attn_kernel(
    const float* __restrict__ Qt, const float* __restrict__ Kt,
    const float* __restrict__ V, float* __restrict__ O)
{
    extern __shared__ float sm[];
    float* Qs = sm;
    float* Ks = sm + 8192;
    float* Vs = sm + 16384;
    float* Ps = sm + 20480;

    const float SCALEF = 0.051776695296636886f;
    const int tx = threadIdx.x, ty = threadIdx.y;
    const int tid = ty*16 + tx;
    const int qt = blockIdx.x, bh = blockIdx.y;
    const int b = bh >> 4, h = bh & 15;
    const int q0 = qt * 64;

    const float* Qg = Qt + (size_t)(bh*32 + qt) * 8192;
    #pragma unroll
    for (int it = 0; it < 8; it++)
        *(float4*)&Qs[(it*256 + tid)*4] = *(const float4*)&Qg[(it*256 + tid)*4];

    float m[4], l[4], acc2[4][4];
    #pragma unroll
    for (int i = 0; i < 4; i++) {
        m[i] = -1e30f; l[i] = 0.0f;
        #pragma unroll
        for (int j = 0; j < 4; j++) acc2[i][j] = 0.0f;
    }

    for (int kt = 0; kt <= qt; kt++) {
        __syncthreads();
        const float* Kg = Kt + (size_t)(bh*32 + kt) * 8192;
        #pragma unroll
        for (int it = 0; it < 8; it++)
            *(float4*)&Ks[(it*256 + tid)*4] = *(const float4*)&Kg[(it*256 + tid)*4];
        const float* Vg = V + (size_t)(b*NS + kt*64)*NUP + h*64;
        #pragma unroll
        for (int it = 0; it < 4; it++) {
            int e = it*256 + tid;
            int key = e >> 4, d0 = (e & 15)*4;
            *(float4*)&Vs[key*64 + d0] = *(const float4*)&Vg[(size_t)key*NUP + d0];
        }
        __syncthreads();

        float acc[4][4];
        #pragma unroll
        for (int i = 0; i < 4; i++)
            #pragma unroll
            for (int j = 0; j < 4; j++) acc[i][j] = 0.0f;

        #pragma unroll 4
        for (int dk = 0; dk < 128; dk++) {
            float4 a = *(const float4*)&Qs[dk*64 + ty*4];
            float4 c = *(const float4*)&Ks[dk*64 + tx*4];
            float ar[4] = {a.x, a.y, a.z, a.w};
            float cr[4] = {c.x, c.y, c.z, c.w};
            #pragma unroll
            for (int i = 0; i < 4; i++)
                #pragma unroll
                for (int j = 0; j < 4; j++)
                    acc[i][j] += ar[i] * cr[j];
        }

        const int k0 = kt * 64;
        const bool diag = (kt == qt);
        #pragma unroll
        for (int i = 0; i < 4; i++) {
            int qrow = q0 + ty*4 + i;
            float s[4];
            #pragma unroll
            for (int j = 0; j < 4; j++) {
                float sv = acc[i][j] * SCALEF;
                if (diag && (k0 + tx*4 + j > qrow)) sv = -1e9f;
                s[j] = sv;
            }
            float mx = fmaxf(fmaxf(s[0], s[1]), fmaxf(s[2], s[3]));
            mx = fmaxf(mx, __shfl_xor_sync(0xffffffffu, mx, 1));
            mx = fmaxf(mx, __shfl_xor_sync(0xffffffffu, mx, 2));
            mx = fmaxf(mx, __shfl_xor_sync(0xffffffffu, mx, 4));
            mx = fmaxf(mx, __shfl_xor_sync(0xffffffffu, mx, 8));
            float mnew = fmaxf(m[i], mx);
            float corr = __expf(m[i] - mnew);
            float p[4], ps = 0.0f;
            #pragma unroll
            for (int j = 0; j < 4; j++) { p[j] = __expf(s[j] - mnew); ps += p[j]; }
            ps += __shfl_xor_sync(0xffffffffu, ps, 1);
            ps += __shfl_xor_sync(0xffffffffu, ps, 2);
            ps += __shfl_xor_sync(0xffffffffu, ps, 4);
            ps += __shfl_xor_sync(0xffffffffu, ps, 8);
            l[i] = l[i]*corr + ps;
            m[i] = mnew;
            #pragma unroll
            for (int j = 0; j < 4; j++) acc2[i][j] *= corr;
            #pragma unroll
            for (int j = 0; j < 4; j++)
                Ps[(tx*4 + j)*65 + ty*4 + i] = p[j];
        }
        __syncthreads();

        #pragma unroll 8
        for (int k = 0; k < 64; k++) {
            float4 v = *(const float4*)&Vs[k*64 + tx*4];
            #pragma unroll
            for (int i = 0; i < 4; i++) {
                float a = Ps[k*65 + ty*4 + i];
                acc2[i][0] += a * v.x;
                acc2[i][1] += a * v.y;
                acc2[i][2] += a * v.z;
                acc2[i][3] += a * v.w;
            }
        }
    }

    #pragma unroll
    for (int i = 0; i < 4; i++) {
        float inv = 1.0f / l[i];
        int qrow = q0 + ty*4 + i;
        float4 o;
        o.x = acc2[i][0]*inv; o.y = acc2[i][1]*inv;
        o.z = acc2[i][2]*inv; o.w = acc2[i][3]*inv;
        *(float4*)&O[(size_t)(b*NS + qrow)*NUP + h*64 + tx*4] = o;
    }
}

// ---------------- host launcher ----------------
extern "C" void kernel_launch(void* const* d_in, const int* in_sizes, int n_in,
                              void* d_out, int out_size)
{
    (void)in_sizes; (void)n_in; (void)out_size;
    const float* X     = (const float*)d_in[0];
    const float* W_dkv = (const float*)d_in[2];
    const float* b_dkv = (const float*)d_in[3];
    const float* W_dq  = (const float*)d_in[4];
    const float* b_dq  = (const float*)d_in[5];
    const float* W_uk  = (const float*)d_in[6];
    const float* b_uk  = (const float*)d_in[7];
    const float* W_uv  = (const float*)d_in[8];
    const float* b_uv  = (const float*)d_in[9];
    const float* W_uq  = (const float*)d_in[10];
    const float* b_uq  = (const float*)d_in[11];
    const float* W_qr  = (const float*)d_in[12];
    const float* b_qr  = (const float*)d_in[13];
    const float* W_kr  = (const float*)d_in[14];
    const float* b_kr  = (const float*)d_in[15];
    const float* W_fc  = (const float*)d_in[16];
    const float* b_fc  = (const float*)d_in[17];
    float* out = (float*)d_out;

    float *ckv, *cq, *kc, *vc, *qc, *qrr, *kr, *Qt, *Kt, *ao;
    float *wt_dkv, *wt_dq, *wt_uk, *wt_uv, *wt_uq, *wt_qr, *wt_fc;
    cudaGetSymbolAddress((void**)&ckv, g_ckv);
    cudaGetSymbolAddress((void**)&cq,  g_cq);
    cudaGetSymbolAddress((void**)&kc,  g_kc);
    cudaGetSymbolAddress((void**)&vc,  g_vc);
    cudaGetSymbolAddress((void**)&qc,  g_qc);
    cudaGetSymbolAddress((void**)&qrr, g_qrr);
    cudaGetSymbolAddress((void**)&kr,  g_kr);
    cudaGetSymbolAddress((void**)&Qt,  g_Qt);
    cudaGetSymbolAddress((void**)&Kt,  g_Kt);
    cudaGetSymbolAddress((void**)&ao,  g_ao);
    cudaGetSymbolAddress((void**)&wt_dkv, g_Wt_dkv);
    cudaGetSymbolAddress((void**)&wt_dq,  g_Wt_dq);
    cudaGetSymbolAddress((void**)&wt_uk,  g_Wt_uk);
    cudaGetSymbolAddress((void**)&wt_uv,  g_Wt_uv);
    cudaGetSymbolAddress((void**)&wt_uq,  g_Wt_uq);
    cudaGetSymbolAddress((void**)&wt_qr,  g_Wt_qr);
    cudaGetSymbolAddress((void**)&wt_fc,  g_Wt_fc);

    dim3 tblk(32, 8);
    transpose_k<<<dim3(NDOWN/32, NHID/32), tblk>>>(W_dkv, wt_dkv, NHID, NDOWN);
    transpose_k<<<dim3(NDOWN/32, NHID/32), tblk>>>(W_dq,  wt_dq,  NHID, NDOWN);
    transpose_k<<<dim3(NUP/32, NDOWN/32), tblk>>>(W_uk, wt_uk, NDOWN, NUP);
    transpose_k<<<dim3(NUP/32, NDOWN/32), tblk>>>(W_uv, wt_uv, NDOWN, NUP);
    transpose_k<<<dim3(NUP/32, NDOWN/32), tblk>>>(W_uq, wt_uq, NDOWN, NUP);
    transpose_k<<<dim3(NUP/32, NDOWN/32), tblk>>>(W_qr, wt_qr, NDOWN, NUP);
    transpose_k<<<dim3(NHID/32, NUP/32), tblk>>>(W_fc, wt_fc, NUP, NHID);

    const int GSM = 4 * BUFSZ * 4;  // 73728 bytes
    cudaFuncSetAttribute(mma_gemm, cudaFuncAttributeMaxDynamicSharedMemorySize, GSM);

    // down projections (tf32 tensor cores)
    mma_gemm<<<dim3(NDOWN/128, NBS/128), 256, GSM>>>(X, wt_dkv, b_dkv, ckv, NDOWN, NHID);
    mma_gemm<<<dim3(NDOWN/128, NBS/128), 256, GSM>>>(X, wt_dq,  b_dq,  cq,  NDOWN, NHID);
    // small rope-k projection (fp32)
    sgemm_bias<<<dim3(NROPE/64, NBS/64), dim3(16,16)>>>(X, W_kr, b_kr, kr, NBS, NROPE, NHID);
    // up projections
    mma_gemm<<<dim3(NUP/128, NBS/128), 256, GSM>>>(ckv, wt_uk, b_uk, kc,  NUP, NDOWN);
    mma_gemm<<<dim3(NUP/128, NBS/128), 256, GSM>>>(ckv, wt_uv, b_uv, vc,  NUP, NDOWN);
    mma_gemm<<<dim3(NUP/128, NBS/128), 256, GSM>>>(cq,  wt_uq, b_uq, qc,  NUP, NDOWN);
    mma_gemm<<<dim3(NUP/128, NBS/128), 256, GSM>>>(cq,  wt_qr, b_qr, qrr, NUP, NDOWN);
    // rope + pack into transposed per-tile layout
    pack_qk<<<dim3(32, 64), 256>>>(kc, qc, qrr, kr, Qt, Kt);
    // causal flash attention (fp32)
    const int SMEM = (8192 + 8192 + 4096 + 64*65) * 4;
    cudaFuncSetAttribute(attn_kernel, cudaFuncAttributeMaxDynamicSharedMemorySize, SMEM);
    attn_kernel<<<dim3(32, 64), dim3(16,16), SMEM>>>(Qt, Kt, vc, ao);
    // final projection
    mma_gemm<<<dim3(NHID/128, NBS/128), 256, GSM>>>(ao, wt_fc, b_fc, out, NHID, NUP);
}

// round 6
// speedup vs baseline: 2.6976x; 1.6369x over previous
#include <cuda_runtime.h>
#include <math.h>
#include <stdint.h>

// Problem constants
#define NB    4
#define NS    2048
#define NHID  2048
#define NDOWN 512
#define NUP   1024
#define NH    16
#define NROPE 64
#define NBS   (NB*NS)          // 8192 tokens

// ---------------- scratch (device globals; no runtime alloc allowed) ----------------
__device__ float g_ckv[NBS*NDOWN];
__device__ float g_cq [NBS*NDOWN];
__device__ float g_kc [NBS*NUP];
__device__ float g_vc [NBS*NUP];
__device__ float g_qc [NBS*NUP];
__device__ float g_qrr[NBS*NUP];
__device__ float g_kr [NBS*NROPE];
__device__ float g_Qn [NB*NH*NS*128];   // [bh][s][128]
__device__ float g_Kn [NB*NH*NS*128];   // [bh][s][128]
__device__ float g_Vt [NB*NH*64*NS];    // [bh][dv][s]
__device__ float g_ao [NBS*NUP];

// transposed weights [N,K]
__device__ float g_Wt_dkv[NDOWN*NHID];
__device__ float g_Wt_dq [NDOWN*NHID];
__device__ float g_Wt_uk [NUP*NDOWN];
__device__ float g_Wt_uv [NUP*NDOWN];
__device__ float g_Wt_uq [NUP*NDOWN];
__device__ float g_Wt_qr [NUP*NDOWN];
__device__ float g_Wt_fc [NHID*NUP];

// ---------------- helpers ----------------
__device__ __forceinline__ uint32_t tf32r(float x) {
    uint32_t u;
    asm("cvt.rna.tf32.f32 %0, %1;" : "=r"(u) : "f"(x));
    return u;
}
__device__ __forceinline__ void mma_tf32_16n8k8(
    float& c0, float& c1, float& c2, float& c3,
    uint32_t a0, uint32_t a1, uint32_t a2, uint32_t a3,
    uint32_t b0, uint32_t b1)
{
    asm volatile(
        "mma.sync.aligned.m16n8k8.row.col.f32.tf32.tf32.f32 "
        "{%0,%1,%2,%3}, {%4,%5,%6,%7}, {%8,%9}, {%0,%1,%2,%3};"
        : "+f"(c0), "+f"(c1), "+f"(c2), "+f"(c3)
        : "r"(a0), "r"(a1), "r"(a2), "r"(a3), "r"(b0), "r"(b1));
}

// ---------------- weight transpose: Wt[n*K+k] = W[k*N+n] ----------------
__global__ __launch_bounds__(256) void transpose_k(
    const float* __restrict__ W, float* __restrict__ Wt, int K, int N)
{
    __shared__ float t[32][33];
    int n0 = blockIdx.x * 32, k0 = blockIdx.y * 32;
    int tx = threadIdx.x, ty = threadIdx.y;
    #pragma unroll
    for (int i = ty; i < 32; i += 8)
        t[i][tx] = W[(size_t)(k0 + i) * N + n0 + tx];
    __syncthreads();
    #pragma unroll
    for (int i = ty; i < 32; i += 8)
        Wt[(size_t)(n0 + i) * K + k0 + tx] = t[tx][i];
}

// ---------------- tf32 mma.sync GEMM: C[M,N] = A[M,K] @ Wt[N,K]^T + bias ------------
#define STRD 36
#define BUFSZ (128*STRD)
__global__ __launch_bounds__(256) void mma_gemm(
    const float* __restrict__ A, const float* __restrict__ Wt,
    const float* __restrict__ bias, float* __restrict__ C,
    int N, int K)
{
    extern __shared__ float sm[];
    float* As = sm;
    float* Bs = sm + 2*BUFSZ;

    const int tid = threadIdx.x;
    const int w = tid >> 5, lane = tid & 31;
    const int g = lane >> 2, tig = lane & 3;
    const int wm = (w & 1) * 64;
    const int wn = (w >> 1) * 32;
    const int M0 = blockIdx.y * 128, N0 = blockIdx.x * 128;

    const float* Ag = A  + (size_t)M0 * K;
    const float* Bg = Wt + (size_t)N0 * K;

    float acc[4][4][4];
    #pragma unroll
    for (int mt = 0; mt < 4; mt++)
        #pragma unroll
        for (int nt = 0; nt < 4; nt++)
            #pragma unroll
            for (int q = 0; q < 4; q++) acc[mt][nt][q] = 0.0f;

    const int row_ld = tid >> 3;
    const int kc_ld  = (tid & 7) * 4;

    {
        #pragma unroll
        for (int it = 0; it < 4; it++) {
            int row = it * 32 + row_ld;
            float4 va = *(const float4*)(Ag + (size_t)row * K + kc_ld);
            float4 vb = *(const float4*)(Bg + (size_t)row * K + kc_ld);
            float* da = As + row * STRD + kc_ld;
            float* db = Bs + row * STRD + kc_ld;
            da[0] = __uint_as_float(tf32r(va.x));
            da[1] = __uint_as_float(tf32r(va.y));
            da[2] = __uint_as_float(tf32r(va.z));
            da[3] = __uint_as_float(tf32r(va.w));
            db[0] = __uint_as_float(tf32r(vb.x));
            db[1] = __uint_as_float(tf32r(vb.y));
            db[2] = __uint_as_float(tf32r(vb.z));
            db[3] = __uint_as_float(tf32r(vb.w));
        }
    }
    __syncthreads();

    const int NC = K >> 5;
    for (int ch = 0; ch < NC; ch++) {
        const int buf = ch & 1;
        const float* Ab = As + buf * BUFSZ;
        const float* Bb = Bs + buf * BUFSZ;

        float4 ra[4], rb[4];
        const bool more = (ch + 1 < NC);
        if (more) {
            const int kc0 = (ch + 1) * 32;
            #pragma unroll
            for (int it = 0; it < 4; it++) {
                int row = it * 32 + row_ld;
                ra[it] = *(const float4*)(Ag + (size_t)row * K + kc0 + kc_ld);
                rb[it] = *(const float4*)(Bg + (size_t)row * K + kc0 + kc_ld);
            }
        }

        #pragma unroll
        for (int ks = 0; ks < 4; ks++) {
            const int k0 = ks * 8;
            uint32_t af[4][4], bf[4][2];
            #pragma unroll
            for (int mt = 0; mt < 4; mt++) {
                const float* p = Ab + (wm + mt * 16 + g) * STRD + k0 + tig;
                af[mt][0] = __float_as_uint(p[0]);
                af[mt][1] = __float_as_uint(p[8 * STRD]);
                af[mt][2] = __float_as_uint(p[4]);
                af[mt][3] = __float_as_uint(p[8 * STRD + 4]);
            }
            #pragma unroll
            for (int nt = 0; nt < 4; nt++) {
                const float* p = Bb + (wn + nt * 8 + g) * STRD + k0 + tig;
                bf[nt][0] = __float_as_uint(p[0]);
                bf[nt][1] = __float_as_uint(p[4]);
            }
            #pragma unroll
            for (int mt = 0; mt < 4; mt++)
                #pragma unroll
                for (int nt = 0; nt < 4; nt++)
                    mma_tf32_16n8k8(acc[mt][nt][0], acc[mt][nt][1],
                                    acc[mt][nt][2], acc[mt][nt][3],
                                    af[mt][0], af[mt][1], af[mt][2], af[mt][3],
                                    bf[nt][0], bf[nt][1]);
        }

        if (more) {
            float* da0 = As + (buf ^ 1) * BUFSZ;
            float* db0 = Bs + (buf ^ 1) * BUFSZ;
            #pragma unroll
            for (int it = 0; it < 4; it++) {
                int row = it * 32 + row_ld;
                float* da = da0 + row * STRD + kc_ld;
                float* db = db0 + row * STRD + kc_ld;
                da[0] = __uint_as_float(tf32r(ra[it].x));
                da[1] = __uint_as_float(tf32r(ra[it].y));
                da[2] = __uint_as_float(tf32r(ra[it].z));
                da[3] = __uint_as_float(tf32r(ra[it].w));
                db[0] = __uint_as_float(tf32r(rb[it].x));
                db[1] = __uint_as_float(tf32r(rb[it].y));
                db[2] = __uint_as_float(tf32r(rb[it].z));
                db[3] = __uint_as_float(tf32r(rb[it].w));
            }
        }
        __syncthreads();
    }

    #pragma unroll
    for (int mt = 0; mt < 4; mt++) {
        const int row = M0 + wm + mt * 16 + g;
        #pragma unroll
        for (int nt = 0; nt < 4; nt++) {
            const int col = N0 + wn + nt * 8 + 2 * tig;
            float b0 = bias[col], b1 = bias[col + 1];
            float2 o0; o0.x = acc[mt][nt][0] + b0; o0.y = acc[mt][nt][1] + b1;
            float2 o1; o1.x = acc[mt][nt][2] + b0; o1.y = acc[mt][nt][3] + b1;
            *(float2*)(C + (size_t)row * N + col)       = o0;
            *(float2*)(C + (size_t)(row + 8) * N + col) = o1;
        }
    }
}

// ---------------- fp32 SGEMM (small W_kr projection) ----------------
__global__ __launch_bounds__(256) void sgemm_bias(
    const float* __restrict__ A, const float* __restrict__ Bm,
    const float* __restrict__ bias, float* __restrict__ C,
    int M, int N, int K)
{
    __shared__ float Ash[16*68];
    __shared__ float Bsh[16*64];

    const int tx = threadIdx.x, ty = threadIdx.y;
    const int tid = ty*16 + tx;
    const int mBase = blockIdx.y*64, nBase = blockIdx.x*64;

    const int arow = tid >> 2;
    const int ak4  = (tid & 3) * 4;
    const int brow = tid >> 4;
    const int bcol = (tid & 15) * 4;

    const float* Ap = A + (size_t)(mBase + arow)*K + ak4;
    const float* Bp = Bm + (size_t)brow*N + nBase + bcol;

    float acc[4][4];
    #pragma unroll
    for (int i = 0; i < 4; i++)
        #pragma unroll
        for (int j = 0; j < 4; j++) acc[i][j] = 0.0f;

    for (int kt = 0; kt < K; kt += 16) {
        float4 av = *(const float4*)(Ap + kt);
        float4 bv = *(const float4*)(Bp + (size_t)kt*N);
        Ash[(ak4+0)*68 + arow] = av.x;
        Ash[(ak4+1)*68 + arow] = av.y;
        Ash[(ak4+2)*68 + arow] = av.z;
        Ash[(ak4+3)*68 + arow] = av.w;
        *(float4*)&Bsh[brow*64 + bcol] = bv;
        __syncthreads();

        #pragma unroll
        for (int kk = 0; kk < 16; kk++) {
            float4 a = *(const float4*)&Ash[kk*68 + ty*4];
            float4 b = *(const float4*)&Bsh[kk*64 + tx*4];
            float ar[4] = {a.x, a.y, a.z, a.w};
            float br[4] = {b.x, b.y, b.z, b.w};
            #pragma unroll
            for (int i = 0; i < 4; i++)
                #pragma unroll
                for (int j = 0; j < 4; j++)
                    acc[i][j] += ar[i] * br[j];
        }
        __syncthreads();
    }

    float4 bb = *(const float4*)&bias[nBase + tx*4];
    float bbr[4] = {bb.x, bb.y, bb.z, bb.w};
    #pragma unroll
    for (int i = 0; i < 4; i++) {
        float4 o;
        o.x = acc[i][0] + bbr[0];
        o.y = acc[i][1] + bbr[1];
        o.z = acc[i][2] + bbr[2];
        o.w = acc[i][3] + bbr[3];
        *(float4*)&C[(size_t)(mBase + ty*4 + i)*N + nBase + tx*4] = o;
    }
}

// ---------------- pack + RoPE: natural layout Qn/Kn [bh][s][128] ----------------
__global__ __launch_bounds__(256) void pack_qk(
    const float* __restrict__ kc, const float* __restrict__ qc,
    const float* __restrict__ qr, const float* __restrict__ kr,
    float* __restrict__ Qn, float* __restrict__ Kn)
{
    const int st = blockIdx.x;   // 64-token tiles
    const int bh = blockIdx.y;
    const int b  = bh >> 4, h = bh & 15;
    const int s0 = st * 64;
    float* Qo = Qn + ((size_t)bh*NS + s0) * 128;
    float* Ko = Kn + ((size_t)bh*NS + s0) * 128;

    for (int it = 0; it < 32; it++) {
        int e = it*256 + threadIdx.x;   // 0..8191
        int sl = e >> 7, d = e & 127;
        int s = s0 + sl;
        int row = b*NS + s;
        float kval, qval;
        if (d < 64) {
            kval = kc[(size_t)row*NUP + h*64 + d];
            qval = qc[(size_t)row*NUP + h*64 + d];
        } else {
            int dd = d - 64;
            int i2 = dd & ~1;
            float fr = powf(10000.0f, -((float)i2) / 64.0f);
            float th = (float)s * fr;
            float cs, sn;
            sincosf(th, &sn, &cs);
            float kx1 = kr[(size_t)row*NROPE + i2];
            float kx2 = kr[(size_t)row*NROPE + i2 + 1];
            float qx1 = qr[(size_t)row*NUP + h*64 + i2];
            float qx2 = qr[(size_t)row*NUP + h*64 + i2 + 1];
            if (dd & 1) { kval = kx2*cs + kx1*sn; qval = qx2*cs + qx1*sn; }
            else        { kval = kx1*cs - kx2*sn; qval = qx1*cs - qx2*sn; }
        }
        Ko[e] = kval;
        Qo[e] = qval;
    }
}

// ---------------- pack V transposed: Vt[bh][dv][s] = vc[b*S+s][h*64+dv] ----------------
__global__ __launch_bounds__(256) void pack_vt(
    const float* __restrict__ vc, float* __restrict__ Vt)
{
    __shared__ float t[64*65];
    const int st = blockIdx.x;
    const int bh = blockIdx.y;
    const int b  = bh >> 4, h = bh & 15;
    const int s0 = st * 64;
    const int tid = threadIdx.x;

    for (int it = 0; it < 16; it++) {
        int e = it*256 + tid;          // 0..4095
        int sl = e >> 6, dv = e & 63;
        t[sl*65 + dv] = vc[((size_t)(b*NS + s0 + sl))*NUP + h*64 + dv];
    }
    __syncthreads();
    for (int it = 0; it < 16; it++) {
        int e = it*256 + tid;
        int dv = e >> 6, sq = e & 63;
        Vt[((size_t)bh*64 + dv)*NS + s0 + sq] = t[sq*65 + dv];
    }
}

// ---------------- tf32 mma flash attention (conservative variant) ----------------
// CTA: 128 q rows x one (b,h). 8 warps x 16 rows. K-tiles of 64 keys.
#define KSTR 132
#define VSTR 68
#define PSTR 68
__global__ __launch_bounds__(256) void attn_mma(
    const float* __restrict__ Qn, const float* __restrict__ Kn,
    const float* __restrict__ Vt, float* __restrict__ O)
{
    extern __shared__ float sm[];
    float* Ks = sm;                 // [64][132] = 8448
    float* Vs = sm + 8448;          // [64][68]  = 4352
    float* Ps = sm + 12800;         // 8 x [16][68] = 8704   (total 21504 floats)

    const int tid = threadIdx.x;
    const int w = tid >> 5, lane = tid & 31;
    const int g = lane >> 2, tig = lane & 3;
    const int qt = blockIdx.x;
    const int bh = blockIdx.y;
    const int b = bh >> 4, h = bh & 15;
    const int q0 = qt * 128;
    const int rowbase = q0 + w * 16;
    const float SCALEF = 0.051776695296636886f;

    // ---- load Q fragments (prescaled, tf32) straight from gmem ----
    uint32_t qa[16][4];
    {
        const int qr0 = min(rowbase + g,     NS - 1);
        const int qr1 = min(rowbase + g + 8, NS - 1);
        const float* Qg  = Qn + ((size_t)bh * NS + qr0) * 128;
        const float* Qg8 = Qn + ((size_t)bh * NS + qr1) * 128;
        #pragma unroll
        for (int ks = 0; ks < 16; ks++) {
            qa[ks][0] = tf32r(Qg [8*ks + tig]     * SCALEF);
            qa[ks][1] = tf32r(Qg8[8*ks + tig]     * SCALEF);
            qa[ks][2] = tf32r(Qg [8*ks + tig + 4] * SCALEF);
            qa[ks][3] = tf32r(Qg8[8*ks + tig + 4] * SCALEF);
        }
    }

    float m0 = -1e30f, m1 = -1e30f, l0 = 0.0f, l1 = 0.0f;
    float of[8][4];
    #pragma unroll
    for (int nf = 0; nf < 8; nf++)
        #pragma unroll
        for (int c = 0; c < 4; c++) of[nf][c] = 0.0f;

    float* Pw = Ps + w * 16 * PSTR;
    const int nkt = 2*qt + 2;       // number of 64-key tiles

    for (int kt = 0; kt < nkt; kt++) {
        const int k0g = kt * 64;
        __syncthreads();   // prior PV done before refill
        // fill K tile [64 keys][132] (tf32, scalar stores, clamped rows)
        {
            const float* Kg = Kn + (size_t)bh * NS * 128;
            for (int it = 0; it < 32; it++) {
                int e = it*256 + tid;          // 0..8191
                int key = e >> 7, d = e & 127;
                int krow = min(k0g + key, NS - 1);
                Ks[key*KSTR + d] = __uint_as_float(tf32r(Kg[(size_t)krow*128 + d]));
            }
        }
        // fill V tile [64 dv][68] (tf32, scalar stores, clamped cols)
        {
            const float* Vg = Vt + (size_t)bh*64*NS;
            for (int it = 0; it < 16; it++) {
                int e = it*256 + tid;          // 0..4095
                int dv = e >> 6, kq = e & 63;
                int kcol = min(k0g + kq, NS - 1);
                Vs[dv*VSTR + kq] = __uint_as_float(tf32r(Vg[(size_t)dv*NS + kcol]));
            }
        }
        __syncthreads();

        // ---- S = Q @ K^T ----
        float sf[8][4];
        #pragma unroll
        for (int nf = 0; nf < 8; nf++)
            #pragma unroll
            for (int c = 0; c < 4; c++) sf[nf][c] = 0.0f;

        #pragma unroll
        for (int ks = 0; ks < 16; ks++) {
            #pragma unroll
            for (int nf = 0; nf < 8; nf++) {
                const float* bp = Ks + (nf*8 + g)*KSTR + 8*ks + tig;
                uint32_t b0 = __float_as_uint(bp[0]);
                uint32_t b1 = __float_as_uint(bp[4]);
                mma_tf32_16n8k8(sf[nf][0], sf[nf][1], sf[nf][2], sf[nf][3],
                                qa[ks][0], qa[ks][1], qa[ks][2], qa[ks][3], b0, b1);
            }
        }

        // ---- mask + online softmax (rows g, g+8 per thread; quad reduce) ----
        const int row0 = rowbase + g, row1 = row0 + 8;
        if (k0g + 63 > rowbase) {
            #pragma unroll
            for (int nf = 0; nf < 8; nf++) {
                int col = k0g + nf*8 + 2*tig;
                if (col     > row0) sf[nf][0] = -1e9f;
                if (col + 1 > row0) sf[nf][1] = -1e9f;
                if (col     > row1) sf[nf][2] = -1e9f;
                if (col + 1 > row1) sf[nf][3] = -1e9f;
            }
        }
        float mx0 = -1e30f, mx1 = -1e30f;
        #pragma unroll
        for (int nf = 0; nf < 8; nf++) {
            mx0 = fmaxf(mx0, fmaxf(sf[nf][0], sf[nf][1]));
            mx1 = fmaxf(mx1, fmaxf(sf[nf][2], sf[nf][3]));
        }
        mx0 = fmaxf(mx0, __shfl_xor_sync(0xffffffffu, mx0, 1));
        mx0 = fmaxf(mx0, __shfl_xor_sync(0xffffffffu, mx0, 2));
        mx1 = fmaxf(mx1, __shfl_xor_sync(0xffffffffu, mx1, 1));
        mx1 = fmaxf(mx1, __shfl_xor_sync(0xffffffffu, mx1, 2));
        float mn0 = fmaxf(m0, mx0), mn1 = fmaxf(m1, mx1);
        float cr0 = __expf(m0 - mn0), cr1 = __expf(m1 - mn1);
        float ps0 = 0.0f, ps1 = 0.0f;
        #pragma unroll
        for (int nf = 0; nf < 8; nf++) {
            sf[nf][0] = __expf(sf[nf][0] - mn0);
            sf[nf][1] = __expf(sf[nf][1] - mn0);
            sf[nf][2] = __expf(sf[nf][2] - mn1);
            sf[nf][3] = __expf(sf[nf][3] - mn1);
            ps0 += sf[nf][0] + sf[nf][1];
            ps1 += sf[nf][2] + sf[nf][3];
        }
        ps0 += __shfl_xor_sync(0xffffffffu, ps0, 1);
        ps0 += __shfl_xor_sync(0xffffffffu, ps0, 2);
        ps1 += __shfl_xor_sync(0xffffffffu, ps1, 1);
        ps1 += __shfl_xor_sync(0xffffffffu, ps1, 2);
        l0 = l0*cr0 + ps0;  m0 = mn0;
        l1 = l1*cr1 + ps1;  m1 = mn1;

        // rescale O, stash P (tf32) in per-warp smem
        #pragma unroll
        for (int nf = 0; nf < 8; nf++) {
            of[nf][0] *= cr0; of[nf][1] *= cr0;
            of[nf][2] *= cr1; of[nf][3] *= cr1;
            int col = nf*8 + 2*tig;
            Pw[g*PSTR + col]           = __uint_as_float(tf32r(sf[nf][0]));
            Pw[g*PSTR + col + 1]       = __uint_as_float(tf32r(sf[nf][1]));
            Pw[(g+8)*PSTR + col]       = __uint_as_float(tf32r(sf[nf][2]));
            Pw[(g+8)*PSTR + col + 1]   = __uint_as_float(tf32r(sf[nf][3]));
        }
        __syncthreads();

        // ---- O += P @ V ----
        #pragma unroll
        for (int ks = 0; ks < 8; ks++) {
            uint32_t a0 = __float_as_uint(Pw[g*PSTR + 8*ks + tig]);
            uint32_t a1 = __float_as_uint(Pw[(g+8)*PSTR + 8*ks + tig]);
            uint32_t a2 = __float_as_uint(Pw[g*PSTR + 8*ks + tig + 4]);
            uint32_t a3 = __float_as_uint(Pw[(g+8)*PSTR + 8*ks + tig + 4]);
            #pragma unroll
            for (int nf = 0; nf < 8; nf++) {
                const float* vp = Vs + (nf*8 + g)*VSTR + 8*ks + tig;
                uint32_t b0 = __float_as_uint(vp[0]);
                uint32_t b1 = __float_as_uint(vp[4]);
                mma_tf32_16n8k8(of[nf][0], of[nf][1], of[nf][2], of[nf][3],
                                a0, a1, a2, a3, b0, b1);
            }
        }
    }

    // ---- normalize + write out [token][h*64+dv] ----
    const float inv0 = 1.0f / l0, inv1 = 1.0f / l1;
    const int tok0 = b*NS + rowbase + g;
    #pragma unroll
    for (int nf = 0; nf < 8; nf++) {
        int col = h*64 + nf*8 + 2*tig;
        O[(size_t)tok0 * NUP + col]         = of[nf][0]*inv0;
        O[(size_t)tok0 * NUP + col + 1]     = of[nf][1]*inv0;
        O[(size_t)(tok0+8) * NUP + col]     = of[nf][2]*inv1;
        O[(size_t)(tok0+8) * NUP + col + 1] = of[nf][3]*inv1;
    }
}

// ---------------- host launcher ----------------
extern "C" void kernel_launch(void* const* d_in, const int* in_sizes, int n_in,
                              void* d_out, int out_size)
{
    (void)in_sizes; (void)n_in; (void)out_size;
    const float* X     = (const float*)d_in[0];
    const float* W_dkv = (const float*)d_in[2];
    const float* b_dkv = (const float*)d_in[3];
    const float* W_dq  = (const float*)d_in[4];
    const float* b_dq  = (const float*)d_in[5];
    const float* W_uk  = (const float*)d_in[6];
    const float* b_uk  = (const float*)d_in[7];
    const float* W_uv  = (const float*)d_in[8];
    const float* b_uv  = (const float*)d_in[9];
    const float* W_uq  = (const float*)d_in[10];
    const float* b_uq  = (const float*)d_in[11];
    const float* W_qr  = (const float*)d_in[12];
    const float* b_qr  = (const float*)d_in[13];
    const float* W_kr  = (const float*)d_in[14];
    const float* b_kr  = (const float*)d_in[15];
    const float* W_fc  = (const float*)d_in[16];
    const float* b_fc  = (const float*)d_in[17];
    float* out = (float*)d_out;

    float *ckv, *cq, *kc, *vc, *qc, *qrr, *kr, *Qn, *Kn, *Vt, *ao;
    float *wt_dkv, *wt_dq, *wt_uk, *wt_uv, *wt_uq, *wt_qr, *wt_fc;
    cudaGetSymbolAddress((void**)&ckv, g_ckv);
    cudaGetSymbolAddress((void**)&cq,  g_cq);
    cudaGetSymbolAddress((void**)&kc,  g_kc);
    cudaGetSymbolAddress((void**)&vc,  g_vc);
    cudaGetSymbolAddress((void**)&qc,  g_qc);
    cudaGetSymbolAddress((void**)&qrr, g_qrr);
    cudaGetSymbolAddress((void**)&kr,  g_kr);
    cudaGetSymbolAddress((void**)&Qn,  g_Qn);
    cudaGetSymbolAddress((void**)&Kn,  g_Kn);
    cudaGetSymbolAddress((void**)&Vt,  g_Vt);
    cudaGetSymbolAddress((void**)&ao,  g_ao);
    cudaGetSymbolAddress((void**)&wt_dkv, g_Wt_dkv);
    cudaGetSymbolAddress((void**)&wt_dq,  g_Wt_dq);
    cudaGetSymbolAddress((void**)&wt_uk,  g_Wt_uk);
    cudaGetSymbolAddress((void**)&wt_uv,  g_Wt_uv);
    cudaGetSymbolAddress((void**)&wt_uq,  g_Wt_uq);
    cudaGetSymbolAddress((void**)&wt_qr,  g_Wt_qr);
    cudaGetSymbolAddress((void**)&wt_fc,  g_Wt_fc);

    dim3 tblk(32, 8);
    transpose_k<<<dim3(NDOWN/32, NHID/32), tblk>>>(W_dkv, wt_dkv, NHID, NDOWN);
    transpose_k<<<dim3(NDOWN/32, NHID/32), tblk>>>(W_dq,  wt_dq,  NHID, NDOWN);
    transpose_k<<<dim3(NUP/32, NDOWN/32), tblk>>>(W_uk, wt_uk, NDOWN, NUP);
    transpose_k<<<dim3(NUP/32, NDOWN/32), tblk>>>(W_uv, wt_uv, NDOWN, NUP);
    transpose_k<<<dim3(NUP/32, NDOWN/32), tblk>>>(W_uq, wt_uq, NDOWN, NUP);
    transpose_k<<<dim3(NUP/32, NDOWN/32), tblk>>>(W_qr, wt_qr, NDOWN, NUP);
    transpose_k<<<dim3(NHID/32, NUP/32), tblk>>>(W_fc, wt_fc, NUP, NHID);

    const int GSM = 4 * BUFSZ * 4;
    cudaFuncSetAttribute(mma_gemm, cudaFuncAttributeMaxDynamicSharedMemorySize, GSM);

    mma_gemm<<<dim3(NDOWN/128, NBS/128), 256, GSM>>>(X, wt_dkv, b_dkv, ckv, NDOWN, NHID);
    mma_gemm<<<dim3(NDOWN/128, NBS/128), 256, GSM>>>(X, wt_dq,  b_dq,  cq,  NDOWN, NHID);
    sgemm_bias<<<dim3(NROPE/64, NBS/64), dim3(16,16)>>>(X, W_kr, b_kr, kr, NBS, NROPE, NHID);
    mma_gemm<<<dim3(NUP/128, NBS/128), 256, GSM>>>(ckv, wt_uk, b_uk, kc,  NUP, NDOWN);
    mma_gemm<<<dim3(NUP/128, NBS/128), 256, GSM>>>(ckv, wt_uv, b_uv, vc,  NUP, NDOWN);
    mma_gemm<<<dim3(NUP/128, NBS/128), 256, GSM>>>(cq,  wt_uq, b_uq, qc,  NUP, NDOWN);
    mma_gemm<<<dim3(NUP/128, NBS/128), 256, GSM>>>(cq,  wt_qr, b_qr, qrr, NUP, NDOWN);

    pack_qk<<<dim3(32, 64), 256>>>(kc, qc, qrr, kr, Qn, Kn);
    pack_vt<<<dim3(32, 64), 256>>>(vc, Vt);

    const int ASM = 21504 * 4;   // 86016 bytes
    cudaFuncSetAttribute(attn_mma, cudaFuncAttributeMaxDynamicSharedMemorySize, ASM);
    attn_mma<<<dim3(16, 64), 256, ASM>>>(Qn, Kn, Vt, ao);

    mma_gemm<<<dim3(NHID/128, NBS/128), 256, GSM>>>(ao, wt_fc, b_fc, out, NHID, NUP);
}

// round 7
// speedup vs baseline: 2.8054x; 1.0399x over previous
#include <cuda_runtime.h>
#include <math.h>
#include <stdint.h>

// Problem constants
#define NB    4
#define NS    2048
#define NHID  2048
#define NDOWN 512
#define NUP   1024
#define NH    16
#define NROPE 64
#define NBS   (NB*NS)          // 8192 tokens

// ---------------- scratch (device globals; no runtime alloc allowed) ----------------
__device__ float g_ckv[NBS*NDOWN];
__device__ float g_cq [NBS*NDOWN];
__device__ float g_kc [NBS*NUP];
__device__ float g_vc [NBS*NUP];
__device__ float g_qc [NBS*NUP];
__device__ float g_qrr[NBS*NUP];
__device__ float g_kr [NBS*NROPE];
__device__ float g_Qn [NB*NH*NS*128];   // [bh][s][128]  tf32-rounded, pre-scaled
__device__ float g_Kn [NB*NH*NS*128];   // [bh][s][128]  tf32-rounded
__device__ float g_Vt [NB*NH*64*NS];    // [bh][dv][s]   tf32-rounded
__device__ float g_ao [NBS*NUP];

// transposed weights [N,K]
__device__ float g_Wt_dkv[NDOWN*NHID];
__device__ float g_Wt_dq [NDOWN*NHID];
__device__ float g_Wt_uk [NUP*NDOWN];
__device__ float g_Wt_uv [NUP*NDOWN];
__device__ float g_Wt_uq [NUP*NDOWN];
__device__ float g_Wt_qr [NUP*NDOWN];
__device__ float g_Wt_fc [NHID*NUP];

// ---------------- helpers ----------------
__device__ __forceinline__ uint32_t tf32r(float x) {
    uint32_t u;
    asm("cvt.rna.tf32.f32 %0, %1;" : "=r"(u) : "f"(x));
    return u;
}
__device__ __forceinline__ void mma_tf32_16n8k8(
    float& c0, float& c1, float& c2, float& c3,
    uint32_t a0, uint32_t a1, uint32_t a2, uint32_t a3,
    uint32_t b0, uint32_t b1)
{
    asm volatile(
        "mma.sync.aligned.m16n8k8.row.col.f32.tf32.tf32.f32 "
        "{%0,%1,%2,%3}, {%4,%5,%6,%7}, {%8,%9}, {%0,%1,%2,%3};"
        : "+f"(c0), "+f"(c1), "+f"(c2), "+f"(c3)
        : "r"(a0), "r"(a1), "r"(a2), "r"(a3), "r"(b0), "r"(b1));
}

// ---------------- weight transpose: Wt[n*K+k] = W[k*N+n] ----------------
__global__ __launch_bounds__(256) void transpose_k(
    const float* __restrict__ W, float* __restrict__ Wt, int K, int N)
{
    __shared__ float t[32][33];
    int n0 = blockIdx.x * 32, k0 = blockIdx.y * 32;
    int tx = threadIdx.x, ty = threadIdx.y;
    #pragma unroll
    for (int i = ty; i < 32; i += 8)
        t[i][tx] = W[(size_t)(k0 + i) * N + n0 + tx];
    __syncthreads();
    #pragma unroll
    for (int i = ty; i < 32; i += 8)
        Wt[(size_t)(n0 + i) * K + k0 + tx] = t[tx][i];
}

// ---------------- tf32 mma.sync GEMM: C[M,N] = A[M,K] @ Wt[N,K]^T + bias ------------
#define STRD 36
#define BUFSZ (128*STRD)
__global__ __launch_bounds__(256) void mma_gemm(
    const float* __restrict__ A, const float* __restrict__ Wt,
    const float* __restrict__ bias, float* __restrict__ C,
    int N, int K)
{
    extern __shared__ float sm[];
    float* As = sm;
    float* Bs = sm + 2*BUFSZ;

    const int tid = threadIdx.x;
    const int w = tid >> 5, lane = tid & 31;
    const int g = lane >> 2, tig = lane & 3;
    const int wm = (w & 1) * 64;
    const int wn = (w >> 1) * 32;
    const int M0 = blockIdx.y * 128, N0 = blockIdx.x * 128;

    const float* Ag = A  + (size_t)M0 * K;
    const float* Bg = Wt + (size_t)N0 * K;

    float acc[4][4][4];
    #pragma unroll
    for (int mt = 0; mt < 4; mt++)
        #pragma unroll
        for (int nt = 0; nt < 4; nt++)
            #pragma unroll
            for (int q = 0; q < 4; q++) acc[mt][nt][q] = 0.0f;

    const int row_ld = tid >> 3;
    const int kc_ld  = (tid & 7) * 4;

    {
        #pragma unroll
        for (int it = 0; it < 4; it++) {
            int row = it * 32 + row_ld;
            float4 va = *(const float4*)(Ag + (size_t)row * K + kc_ld);
            float4 vb = *(const float4*)(Bg + (size_t)row * K + kc_ld);
            uint4 ua; ua.x = tf32r(va.x); ua.y = tf32r(va.y); ua.z = tf32r(va.z); ua.w = tf32r(va.w);
            uint4 ub; ub.x = tf32r(vb.x); ub.y = tf32r(vb.y); ub.z = tf32r(vb.z); ub.w = tf32r(vb.w);
            *(uint4*)(As + row * STRD + kc_ld) = ua;
            *(uint4*)(Bs + row * STRD + kc_ld) = ub;
        }
    }
    __syncthreads();

    const int NC = K >> 5;
    for (int ch = 0; ch < NC; ch++) {
        const int buf = ch & 1;
        const float* Ab = As + buf * BUFSZ;
        const float* Bb = Bs + buf * BUFSZ;

        float4 ra[4], rb[4];
        const bool more = (ch + 1 < NC);
        if (more) {
            const int kc0 = (ch + 1) * 32;
            #pragma unroll
            for (int it = 0; it < 4; it++) {
                int row = it * 32 + row_ld;
                ra[it] = *(const float4*)(Ag + (size_t)row * K + kc0 + kc_ld);
                rb[it] = *(const float4*)(Bg + (size_t)row * K + kc0 + kc_ld);
            }
        }

        #pragma unroll
        for (int ks = 0; ks < 4; ks++) {
            const int k0 = ks * 8;
            uint32_t af[4][4], bf[4][2];
            #pragma unroll
            for (int mt = 0; mt < 4; mt++) {
                const float* p = Ab + (wm + mt * 16 + g) * STRD + k0 + tig;
                af[mt][0] = __float_as_uint(p[0]);
                af[mt][1] = __float_as_uint(p[8 * STRD]);
                af[mt][2] = __float_as_uint(p[4]);
                af[mt][3] = __float_as_uint(p[8 * STRD + 4]);
            }
            #pragma unroll
            for (int nt = 0; nt < 4; nt++) {
                const float* p = Bb + (wn + nt * 8 + g) * STRD + k0 + tig;
                bf[nt][0] = __float_as_uint(p[0]);
                bf[nt][1] = __float_as_uint(p[4]);
            }
            #pragma unroll
            for (int mt = 0; mt < 4; mt++)
                #pragma unroll
                for (int nt = 0; nt < 4; nt++)
                    mma_tf32_16n8k8(acc[mt][nt][0], acc[mt][nt][1],
                                    acc[mt][nt][2], acc[mt][nt][3],
                                    af[mt][0], af[mt][1], af[mt][2], af[mt][3],
                                    bf[nt][0], bf[nt][1]);
        }

        if (more) {
            float* da0 = As + (buf ^ 1) * BUFSZ;
            float* db0 = Bs + (buf ^ 1) * BUFSZ;
            #pragma unroll
            for (int it = 0; it < 4; it++) {
                int row = it * 32 + row_ld;
                uint4 ua; ua.x = tf32r(ra[it].x); ua.y = tf32r(ra[it].y);
                          ua.z = tf32r(ra[it].z); ua.w = tf32r(ra[it].w);
                uint4 ub; ub.x = tf32r(rb[it].x); ub.y = tf32r(rb[it].y);
                          ub.z = tf32r(rb[it].z); ub.w = tf32r(rb[it].w);
                *(uint4*)(da0 + row * STRD + kc_ld) = ua;
                *(uint4*)(db0 + row * STRD + kc_ld) = ub;
            }
        }
        __syncthreads();
    }

    #pragma unroll
    for (int mt = 0; mt < 4; mt++) {
        const int row = M0 + wm + mt * 16 + g;
        #pragma unroll
        for (int nt = 0; nt < 4; nt++) {
            const int col = N0 + wn + nt * 8 + 2 * tig;
            float b0 = bias[col], b1 = bias[col + 1];
            float2 o0; o0.x = acc[mt][nt][0] + b0; o0.y = acc[mt][nt][1] + b1;
            float2 o1; o1.x = acc[mt][nt][2] + b0; o1.y = acc[mt][nt][3] + b1;
            *(float2*)(C + (size_t)row * N + col)       = o0;
            *(float2*)(C + (size_t)(row + 8) * N + col) = o1;
        }
    }
}

// ---------------- fp32 SGEMM (small W_kr projection) ----------------
__global__ __launch_bounds__(256) void sgemm_bias(
    const float* __restrict__ A, const float* __restrict__ Bm,
    const float* __restrict__ bias, float* __restrict__ C,
    int M, int N, int K)
{
    __shared__ float Ash[16*68];
    __shared__ float Bsh[16*64];

    const int tx = threadIdx.x, ty = threadIdx.y;
    const int tid = ty*16 + tx;
    const int mBase = blockIdx.y*64, nBase = blockIdx.x*64;

    const int arow = tid >> 2;
    const int ak4  = (tid & 3) * 4;
    const int brow = tid >> 4;
    const int bcol = (tid & 15) * 4;

    const float* Ap = A + (size_t)(mBase + arow)*K + ak4;
    const float* Bp = Bm + (size_t)brow*N + nBase + bcol;

    float acc[4][4];
    #pragma unroll
    for (int i = 0; i < 4; i++)
        #pragma unroll
        for (int j = 0; j < 4; j++) acc[i][j] = 0.0f;

    for (int kt = 0; kt < K; kt += 16) {
        float4 av = *(const float4*)(Ap + kt);
        float4 bv = *(const float4*)(Bp + (size_t)kt*N);
        Ash[(ak4+0)*68 + arow] = av.x;
        Ash[(ak4+1)*68 + arow] = av.y;
        Ash[(ak4+2)*68 + arow] = av.z;
        Ash[(ak4+3)*68 + arow] = av.w;
        *(float4*)&Bsh[brow*64 + bcol] = bv;
        __syncthreads();

        #pragma unroll
        for (int kk = 0; kk < 16; kk++) {
            float4 a = *(const float4*)&Ash[kk*68 + ty*4];
            float4 b = *(const float4*)&Bsh[kk*64 + tx*4];
            float ar[4] = {a.x, a.y, a.z, a.w};
            float br[4] = {b.x, b.y, b.z, b.w};
            #pragma unroll
            for (int i = 0; i < 4; i++)
                #pragma unroll
                for (int j = 0; j < 4; j++)
                    acc[i][j] += ar[i] * br[j];
        }
        __syncthreads();
    }

    float4 bb = *(const float4*)&bias[nBase + tx*4];
    float bbr[4] = {bb.x, bb.y, bb.z, bb.w};
    #pragma unroll
    for (int i = 0; i < 4; i++) {
        float4 o;
        o.x = acc[i][0] + bbr[0];
        o.y = acc[i][1] + bbr[1];
        o.z = acc[i][2] + bbr[2];
        o.w = acc[i][3] + bbr[3];
        *(float4*)&C[(size_t)(mBase + ty*4 + i)*N + nBase + tx*4] = o;
    }
}

// ---------------- pack + RoPE: Qn/Kn [bh][s][128], tf32-rounded, Q pre-scaled -------
__global__ __launch_bounds__(256) void pack_qk(
    const float* __restrict__ kc, const float* __restrict__ qc,
    const float* __restrict__ qr, const float* __restrict__ kr,
    float* __restrict__ Qn, float* __restrict__ Kn)
{
    const float SCALEF = 0.051776695296636886f;  // 1/(sqrt(128)+sqrt(64))
    const int st = blockIdx.x;   // 64-token tiles
    const int bh = blockIdx.y;
    const int b  = bh >> 4, h = bh & 15;
    const int s0 = st * 64;
    float* Qo = Qn + ((size_t)bh*NS + s0) * 128;
    float* Ko = Kn + ((size_t)bh*NS + s0) * 128;

    for (int it = 0; it < 32; it++) {
        int e = it*256 + threadIdx.x;   // 0..8191
        int sl = e >> 7, d = e & 127;
        int s = s0 + sl;
        int row = b*NS + s;
        float kval, qval;
        if (d < 64) {
            kval = kc[(size_t)row*NUP + h*64 + d];
            qval = qc[(size_t)row*NUP + h*64 + d];
        } else {
            int dd = d - 64;
            int i2 = dd & ~1;
            float fr = powf(10000.0f, -((float)i2) / 64.0f);
            float th = (float)s * fr;
            float cs, sn;
            sincosf(th, &sn, &cs);
            float kx1 = kr[(size_t)row*NROPE + i2];
            float kx2 = kr[(size_t)row*NROPE + i2 + 1];
            float qx1 = qr[(size_t)row*NUP + h*64 + i2];
            float qx2 = qr[(size_t)row*NUP + h*64 + i2 + 1];
            if (dd & 1) { kval = kx2*cs + kx1*sn; qval = qx2*cs + qx1*sn; }
            else        { kval = kx1*cs - kx2*sn; qval = qx1*cs - qx2*sn; }
        }
        Ko[e] = __uint_as_float(tf32r(kval));
        Qo[e] = __uint_as_float(tf32r(qval * SCALEF));
    }
}

// ---------------- pack V transposed: Vt[bh][dv][s], tf32-rounded ----------------
__global__ __launch_bounds__(256) void pack_vt(
    const float* __restrict__ vc, float* __restrict__ Vt)
{
    __shared__ float t[64*65];
    const int st = blockIdx.x;
    const int bh = blockIdx.y;
    const int b  = bh >> 4, h = bh & 15;
    const int s0 = st * 64;
    const int tid = threadIdx.x;

    // phase 1: 64 tokens x 64 dv = 1024 float4 -> 4 iterations of 256 threads
    #pragma unroll
    for (int it = 0; it < 4; it++) {
        int e = it*256 + tid;          // float4 index 0..1023
        int sl = e >> 4, dq = (e & 15) * 4;
        float4 v = *(const float4*)(vc + ((size_t)(b*NS + s0 + sl))*NUP + h*64 + dq);
        t[sl*65 + dq + 0] = v.x;
        t[sl*65 + dq + 1] = v.y;
        t[sl*65 + dq + 2] = v.z;
        t[sl*65 + dq + 3] = v.w;
    }
    __syncthreads();
    // phase 2: transpose out, 1024 float4 -> 4 iterations
    #pragma unroll
    for (int it = 0; it < 4; it++) {
        int e = it*256 + tid;          // float4 index 0..1023
        int dv = e >> 4, sq = (e & 15) * 4;
        uint4 o;
        o.x = tf32r(t[(sq+0)*65 + dv]);
        o.y = tf32r(t[(sq+1)*65 + dv]);
        o.z = tf32r(t[(sq+2)*65 + dv]);
        o.w = tf32r(t[(sq+3)*65 + dv]);
        *(uint4*)(Vt + ((size_t)bh*64 + dv)*NS + s0 + sq) = o;
    }
}

// ---------------- tf32 mma flash attention, double-buffered ----------------
// CTA: 128 q rows x one (b,h). 8 warps x 16 rows. K-tiles of 64 keys.
// smem floats: Kbuf 2x8448 | Vbuf 2x4352 | P 8704  = 34304 floats = 137216 B
#define KSTR 132
#define VSTR 68
#define PSTR 68
__global__ __launch_bounds__(256) void attn_mma(
    const float* __restrict__ Qn, const float* __restrict__ Kn,
    const float* __restrict__ Vt, float* __restrict__ O)
{
    extern __shared__ float sm[];
    float* Kb0 = sm;
    float* Kb1 = sm + 8448;
    float* Vb0 = sm + 16896;
    float* Vb1 = sm + 16896 + 4352;
    float* Ps  = sm + 25600;

    const int tid = threadIdx.x;
    const int w = tid >> 5, lane = tid & 31;
    const int g = lane >> 2, tig = lane & 3;
    const int qt = (int)gridDim.x - 1 - (int)blockIdx.x;   // big tiles first
    const int bh = blockIdx.y;
    const int b = bh >> 4, h = bh & 15;
    const int q0 = qt * 128;
    const int rowbase = q0 + w * 16;

    const float* KgB = Kn + (size_t)bh * NS * 128;
    const float* VgB = Vt + (size_t)bh * 64 * NS;

    // fill-index precompute (vectorized float4)
    const int k_key = tid >> 3, k_dq = (tid & 7) * 16;   // unused pattern; use e-based below

    // ---- load Q fragments straight from gmem (already tf32+scaled) ----
    uint32_t qa[16][4];
    {
        const int qr0 = min(rowbase + g,     NS - 1);
        const int qr1 = min(rowbase + g + 8, NS - 1);
        const float* Qg  = Qn + ((size_t)bh * NS + qr0) * 128;
        const float* Qg8 = Qn + ((size_t)bh * NS + qr1) * 128;
        #pragma unroll
        for (int ks = 0; ks < 16; ks++) {
            qa[ks][0] = __float_as_uint(Qg [8*ks + tig]);
            qa[ks][1] = __float_as_uint(Qg8[8*ks + tig]);
            qa[ks][2] = __float_as_uint(Qg [8*ks + tig + 4]);
            qa[ks][3] = __float_as_uint(Qg8[8*ks + tig + 4]);
        }
    }

    float m0 = -1e30f, m1 = -1e30f, l0 = 0.0f, l1 = 0.0f;
    float of[8][4];
    #pragma unroll
    for (int nf = 0; nf < 8; nf++)
        #pragma unroll
        for (int c = 0; c < 4; c++) of[nf][c] = 0.0f;

    float* Pw = Ps + w * 16 * PSTR;
    const int nkt = 2*qt + 2;       // number of 64-key tiles

    // ---- prologue: fill buffer 0 with tile 0 ----
    {
        #pragma unroll
        for (int it = 0; it < 8; it++) {
            int e = it*256 + tid;                    // f4 index 0..2047
            int key = e >> 5, dq = (e & 31) * 4;
            int krow = min(key, NS - 1);
            *(float4*)(Kb0 + key*KSTR + dq) = *(const float4*)(KgB + (size_t)krow*128 + dq);
        }
        #pragma unroll
        for (int it = 0; it < 4; it++) {
            int e = it*256 + tid;                    // f4 index 0..1023
            int dv = e >> 4, kq = (e & 15) * 4;
            *(float4*)(Vb0 + dv*VSTR + kq) = *(const float4*)(VgB + (size_t)dv*NS + kq);
        }
    }
    __syncthreads();

    for (int kt = 0; kt < nkt; kt++) {
        const int cur = kt & 1;
        const int k0g = kt * 64;
        const float* Kbc = cur ? Kb1 : Kb0;
        const float* Vbc = cur ? Vb1 : Vb0;
        float* Kbn = cur ? Kb0 : Kb1;
        float* Vbn = cur ? Vb0 : Vb1;

        // ---- prefetch next tile into registers (hidden under QK mma) ----
        float4 rk[8], rv[4];
        const bool more = (kt + 1 < nkt);
        if (more) {
            const int kn0 = k0g + 64;
            #pragma unroll
            for (int it = 0; it < 8; it++) {
                int e = it*256 + tid;
                int key = e >> 5, dq = (e & 31) * 4;
                int krow = min(kn0 + key, NS - 1);
                rk[it] = *(const float4*)(KgB + (size_t)krow*128 + dq);
            }
            #pragma unroll
            for (int it = 0; it < 4; it++) {
                int e = it*256 + tid;
                int dv = e >> 4, kq = (e & 15) * 4;
                int kcol = min(kn0 + kq, NS - 4);
                rv[it] = *(const float4*)(VgB + (size_t)dv*NS + kcol);
            }
        }

        // ---- S = Q @ K^T ----
        float sf[8][4];
        #pragma unroll
        for (int nf = 0; nf < 8; nf++)
            #pragma unroll
            for (int c = 0; c < 4; c++) sf[nf][c] = 0.0f;

        #pragma unroll
        for (int ks = 0; ks < 16; ks++) {
            #pragma unroll
            for (int nf = 0; nf < 8; nf++) {
                const float* bp = Kbc + (nf*8 + g)*KSTR + 8*ks + tig;
                uint32_t b0 = __float_as_uint(bp[0]);
                uint32_t b1 = __float_as_uint(bp[4]);
                mma_tf32_16n8k8(sf[nf][0], sf[nf][1], sf[nf][2], sf[nf][3],
                                qa[ks][0], qa[ks][1], qa[ks][2], qa[ks][3], b0, b1);
            }
        }

        // ---- mask + online softmax (rows g, g+8 per thread; quad reduce) ----
        const int row0 = rowbase + g, row1 = row0 + 8;
        if (k0g + 63 > rowbase) {
            #pragma unroll
            for (int nf = 0; nf < 8; nf++) {
                int col = k0g + nf*8 + 2*tig;
                if (col     > row0) sf[nf][0] = -1e9f;
                if (col + 1 > row0) sf[nf][1] = -1e9f;
                if (col     > row1) sf[nf][2] = -1e9f;
                if (col + 1 > row1) sf[nf][3] = -1e9f;
            }
        }
        float mx0 = -1e30f, mx1 = -1e30f;
        #pragma unroll
        for (int nf = 0; nf < 8; nf++) {
            mx0 = fmaxf(mx0, fmaxf(sf[nf][0], sf[nf][1]));
            mx1 = fmaxf(mx1, fmaxf(sf[nf][2], sf[nf][3]));
        }
        mx0 = fmaxf(mx0, __shfl_xor_sync(0xffffffffu, mx0, 1));
        mx0 = fmaxf(mx0, __shfl_xor_sync(0xffffffffu, mx0, 2));
        mx1 = fmaxf(mx1, __shfl_xor_sync(0xffffffffu, mx1, 1));
        mx1 = fmaxf(mx1, __shfl_xor_sync(0xffffffffu, mx1, 2));
        float mn0 = fmaxf(m0, mx0), mn1 = fmaxf(m1, mx1);
        float cr0 = __expf(m0 - mn0), cr1 = __expf(m1 - mn1);
        float ps0 = 0.0f, ps1 = 0.0f;
        #pragma unroll
        for (int nf = 0; nf < 8; nf++) {
            sf[nf][0] = __expf(sf[nf][0] - mn0);
            sf[nf][1] = __expf(sf[nf][1] - mn0);
            sf[nf][2] = __expf(sf[nf][2] - mn1);
            sf[nf][3] = __expf(sf[nf][3] - mn1);
            ps0 += sf[nf][0] + sf[nf][1];
            ps1 += sf[nf][2] + sf[nf][3];
        }
        ps0 += __shfl_xor_sync(0xffffffffu, ps0, 1);
        ps0 += __shfl_xor_sync(0xffffffffu, ps0, 2);
        ps1 += __shfl_xor_sync(0xffffffffu, ps1, 1);
        ps1 += __shfl_xor_sync(0xffffffffu, ps1, 2);
        l0 = l0*cr0 + ps0;  m0 = mn0;
        l1 = l1*cr1 + ps1;  m1 = mn1;

        // rescale O, stash P (tf32) in per-warp smem
        #pragma unroll
        for (int nf = 0; nf < 8; nf++) {
            of[nf][0] *= cr0; of[nf][1] *= cr0;
            of[nf][2] *= cr1; of[nf][3] *= cr1;
            int col = nf*8 + 2*tig;
            Pw[g*PSTR + col]           = __uint_as_float(tf32r(sf[nf][0]));
            Pw[g*PSTR + col + 1]       = __uint_as_float(tf32r(sf[nf][1]));
            Pw[(g+8)*PSTR + col]       = __uint_as_float(tf32r(sf[nf][2]));
            Pw[(g+8)*PSTR + col + 1]   = __uint_as_float(tf32r(sf[nf][3]));
        }
        __syncwarp();

        // ---- drain prefetch regs into the idle buffer ----
        if (more) {
            #pragma unroll
            for (int it = 0; it < 8; it++) {
                int e = it*256 + tid;
                int key = e >> 5, dq = (e & 31) * 4;
                *(float4*)(Kbn + key*KSTR + dq) = rk[it];
            }
            #pragma unroll
            for (int it = 0; it < 4; it++) {
                int e = it*256 + tid;
                int dv = e >> 4, kq = (e & 15) * 4;
                *(float4*)(Vbn + dv*VSTR + kq) = rv[it];
            }
        }

        // ---- O += P @ V ----
        #pragma unroll
        for (int ks = 0; ks < 8; ks++) {
            uint32_t a0 = __float_as_uint(Pw[g*PSTR + 8*ks + tig]);
            uint32_t a1 = __float_as_uint(Pw[(g+8)*PSTR + 8*ks + tig]);
            uint32_t a2 = __float_as_uint(Pw[g*PSTR + 8*ks + tig + 4]);
            uint32_t a3 = __float_as_uint(Pw[(g+8)*PSTR + 8*ks + tig + 4]);
            #pragma unroll
            for (int nf = 0; nf < 8; nf++) {
                const float* vp = Vbc + (nf*8 + g)*VSTR + 8*ks + tig;
                uint32_t b0 = __float_as_uint(vp[0]);
                uint32_t b1 = __float_as_uint(vp[4]);
                mma_tf32_16n8k8(of[nf][0], of[nf][1], of[nf][2], of[nf][3],
                                a0, a1, a2, a3, b0, b1);
            }
        }
        __syncthreads();
    }

    // ---- normalize + write out [token][h*64+dv] ----
    const float inv0 = 1.0f / l0, inv1 = 1.0f / l1;
    const int tok0 = b*NS + rowbase + g;
    #pragma unroll
    for (int nf = 0; nf < 8; nf++) {
        int col = h*64 + nf*8 + 2*tig;
        float2 o0; o0.x = of[nf][0]*inv0; o0.y = of[nf][1]*inv0;
        float2 o1; o1.x = of[nf][2]*inv1; o1.y = of[nf][3]*inv1;
        *(float2*)(O + (size_t)tok0 * NUP + col)     = o0;
        *(float2*)(O + (size_t)(tok0+8) * NUP + col) = o1;
    }
    (void)k_key; (void)k_dq;
}

// ---------------- host launcher ----------------
extern "C" void kernel_launch(void* const* d_in, const int* in_sizes, int n_in,
                              void* d_out, int out_size)
{
    (void)in_sizes; (void)n_in; (void)out_size;
    const float* X     = (const float*)d_in[0];
    const float* W_dkv = (const float*)d_in[2];
    const float* b_dkv = (const float*)d_in[3];
    const float* W_dq  = (const float*)d_in[4];
    const float* b_dq  = (const float*)d_in[5];
    const float* W_uk  = (const float*)d_in[6];
    const float* b_uk  = (const float*)d_in[7];
    const float* W_uv  = (const float*)d_in[8];
    const float* b_uv  = (const float*)d_in[9];
    const float* W_uq  = (const float*)d_in[10];
    const float* b_uq  = (const float*)d_in[11];
    const float* W_qr  = (const float*)d_in[12];
    const float* b_qr  = (const float*)d_in[13];
    const float* W_kr  = (const float*)d_in[14];
    const float* b_kr  = (const float*)d_in[15];
    const float* W_fc  = (const float*)d_in[16];
    const float* b_fc  = (const float*)d_in[17];
    float* out = (float*)d_out;

    float *ckv, *cq, *kc, *vc, *qc, *qrr, *kr, *Qn, *Kn, *Vt, *ao;
    float *wt_dkv, *wt_dq, *wt_uk, *wt_uv, *wt_uq, *wt_qr, *wt_fc;
    cudaGetSymbolAddress((void**)&ckv, g_ckv);
    cudaGetSymbolAddress((void**)&cq,  g_cq);
    cudaGetSymbolAddress((void**)&kc,  g_kc);
    cudaGetSymbolAddress((void**)&vc,  g_vc);
    cudaGetSymbolAddress((void**)&qc,  g_qc);
    cudaGetSymbolAddress((void**)&qrr, g_qrr);
    cudaGetSymbolAddress((void**)&kr,  g_kr);
    cudaGetSymbolAddress((void**)&Qn,  g_Qn);
    cudaGetSymbolAddress((void**)&Kn,  g_Kn);
    cudaGetSymbolAddress((void**)&Vt,  g_Vt);
    cudaGetSymbolAddress((void**)&ao,  g_ao);
    cudaGetSymbolAddress((void**)&wt_dkv, g_Wt_dkv);
    cudaGetSymbolAddress((void**)&wt_dq,  g_Wt_dq);
    cudaGetSymbolAddress((void**)&wt_uk,  g_Wt_uk);
    cudaGetSymbolAddress((void**)&wt_uv,  g_Wt_uv);
    cudaGetSymbolAddress((void**)&wt_uq,  g_Wt_uq);
    cudaGetSymbolAddress((void**)&wt_qr,  g_Wt_qr);
    cudaGetSymbolAddress((void**)&wt_fc,  g_Wt_fc);

    dim3 tblk(32, 8);
    transpose_k<<<dim3(NDOWN/32, NHID/32), tblk>>>(W_dkv, wt_dkv, NHID, NDOWN);
    transpose_k<<<dim3(NDOWN/32, NHID/32), tblk>>>(W_dq,  wt_dq,  NHID, NDOWN);
    transpose_k<<<dim3(NUP/32, NDOWN/32), tblk>>>(W_uk, wt_uk, NDOWN, NUP);
    transpose_k<<<dim3(NUP/32, NDOWN/32), tblk>>>(W_uv, wt_uv, NDOWN, NUP);
    transpose_k<<<dim3(NUP/32, NDOWN/32), tblk>>>(W_uq, wt_uq, NDOWN, NUP);
    transpose_k<<<dim3(NUP/32, NDOWN/32), tblk>>>(W_qr, wt_qr, NDOWN, NUP);
    transpose_k<<<dim3(NHID/32, NUP/32), tblk>>>(W_fc, wt_fc, NUP, NHID);

    const int GSM = 4 * BUFSZ * 4;
    cudaFuncSetAttribute(mma_gemm, cudaFuncAttributeMaxDynamicSharedMemorySize, GSM);

    mma_gemm<<<dim3(NDOWN/128, NBS/128), 256, GSM>>>(X, wt_dkv, b_dkv, ckv, NDOWN, NHID);
    mma_gemm<<<dim3(NDOWN/128, NBS/128), 256, GSM>>>(X, wt_dq,  b_dq,  cq,  NDOWN, NHID);
    sgemm_bias<<<dim3(NROPE/64, NBS/64), dim3(16,16)>>>(X, W_kr, b_kr, kr, NBS, NROPE, NHID);
    mma_gemm<<<dim3(NUP/128, NBS/128), 256, GSM>>>(ckv, wt_uk, b_uk, kc,  NUP, NDOWN);
    mma_gemm<<<dim3(NUP/128, NBS/128), 256, GSM>>>(ckv, wt_uv, b_uv, vc,  NUP, NDOWN);
    mma_gemm<<<dim3(NUP/128, NBS/128), 256, GSM>>>(cq,  wt_uq, b_uq, qc,  NUP, NDOWN);
    mma_gemm<<<dim3(NUP/128, NBS/128), 256, GSM>>>(cq,  wt_qr, b_qr, qrr, NUP, NDOWN);

    pack_qk<<<dim3(32, 64), 256>>>(kc, qc, qrr, kr, Qn, Kn);
    pack_vt<<<dim3(32, 64), 256>>>(vc, Vt);

    const int ASM = 34304 * 4;   // 137216 bytes
    cudaFuncSetAttribute(attn_mma, cudaFuncAttributeMaxDynamicSharedMemorySize, ASM);
    attn_mma<<<dim3(16, 64), 256, ASM>>>(Qn, Kn, Vt, ao);

    mma_gemm<<<dim3(NHID/128, NBS/128), 256, GSM>>>(ao, wt_fc, b_fc, out, NHID, NUP);
}

// round 8
// speedup vs baseline: 3.1663x; 1.1287x over previous
#include <cuda_runtime.h>
#include <math.h>
#include <stdint.h>

// Problem constants
#define NB    4
#define NS    2048
#define NHID  2048
#define NDOWN 512
#define NUP   1024
#define NH    16
#define NROPE 64
#define NBS   (NB*NS)          // 8192 tokens
#define NX    1152             // combined X-proj output width: 512+512+64+64pad

// ---------------- scratch (device globals) ----------------
__device__ float g_cx  [NBS*NX];        // [tok][dkv(512)|dq(512)|kr(64)|pad(64)]
__device__ float g_kcvc[NBS*2048];      // [tok][kc(1024)|vc(1024)]
__device__ float g_qcqr[NBS*2048];      // [tok][qc(1024)|qr(1024)]
__device__ float g_Qn [NB*NH*NS*128];   // [bh][s][128] tf32, pre-scaled
__device__ float g_Kn [NB*NH*NS*128];   // [bh][s][128] tf32
__device__ float g_Vt [NB*NH*64*NS];    // [bh][dv][s]  tf32
__device__ float g_ao [NBS*NUP];

__device__ float g_Wx [NX*NHID];        // [1152][2048]
__device__ float g_Wu1[2048*NDOWN];     // [uk|uv][512]
__device__ float g_Wu2[2048*NDOWN];     // [uq|qr][512]
__device__ float g_Wfc[NHID*NUP];       // [2048][1024]
__device__ float g_bx [NX];
__device__ float g_bu1[2048];
__device__ float g_bu2[2048];

// ---------------- helpers ----------------
__device__ __forceinline__ uint32_t tf32r(float x) {
    uint32_t u;
    asm("cvt.rna.tf32.f32 %0, %1;" : "=r"(u) : "f"(x));
    return u;
}
__device__ __forceinline__ void mma_tf32_16n8k8(
    float& c0, float& c1, float& c2, float& c3,
    uint32_t a0, uint32_t a1, uint32_t a2, uint32_t a3,
    uint32_t b0, uint32_t b1)
{
    asm volatile(
        "mma.sync.aligned.m16n8k8.row.col.f32.tf32.tf32.f32 "
        "{%0,%1,%2,%3}, {%4,%5,%6,%7}, {%8,%9}, {%0,%1,%2,%3};"
        : "+f"(c0), "+f"(c1), "+f"(c2), "+f"(c3)
        : "r"(a0), "r"(a1), "r"(a2), "r"(a3), "r"(b0), "r"(b1));
}

// ---------------- fused weight prep: transposes + bias assembly ----------------
__device__ __forceinline__ void tr_tile(
    const float* __restrict__ W, int srcN,
    float* __restrict__ dst, int dstK, int rowbase,
    int nt, int kt, float (*t)[33], int tx, int ty)
{
    const int n0 = nt * 32, k0 = kt * 32;
    #pragma unroll
    for (int i = ty; i < 32; i += 8)
        t[i][tx] = W[(size_t)(k0 + i) * srcN + n0 + tx];
    __syncthreads();
    #pragma unroll
    for (int i = ty; i < 32; i += 8)
        dst[(size_t)(rowbase + n0 + i) * dstK + k0 + tx] = t[tx][i];
}

__global__ __launch_bounds__(256) void wprep(
    const float* __restrict__ W_dkv, const float* __restrict__ W_dq,
    const float* __restrict__ W_kr,  const float* __restrict__ W_uk,
    const float* __restrict__ W_uv,  const float* __restrict__ W_uq,
    const float* __restrict__ W_qr,  const float* __restrict__ W_fc,
    const float* __restrict__ b_dkv, const float* __restrict__ b_dq,
    const float* __restrict__ b_kr,  const float* __restrict__ b_uk,
    const float* __restrict__ b_uv,  const float* __restrict__ b_uq,
    const float* __restrict__ b_qr)
{
    __shared__ float t[32][33];
    const int tx = threadIdx.x, ty = threadIdx.y;
    const int id = blockIdx.x;

    if (id < 1024) {                       // dkv: n16 x k64
        tr_tile(W_dkv, NDOWN, g_Wx, NHID, 0,    id % 16, id / 16, t, tx, ty);
    } else if (id < 2048) {                // dq
        int r = id - 1024;
        tr_tile(W_dq,  NDOWN, g_Wx, NHID, 512,  r % 16, r / 16, t, tx, ty);
    } else if (id < 2176) {                // kr: n2 x k64
        int r = id - 2048;
        tr_tile(W_kr,  NROPE, g_Wx, NHID, 1024, r % 2, r / 2, t, tx, ty);
    } else if (id < 2304) {                // pad rows 1088-1151: zeros
        int r = id - 2176;
        int n0 = (r % 2) * 32, k0 = (r / 2) * 32;
        #pragma unroll
        for (int i = ty; i < 32; i += 8)
            g_Wx[(size_t)(1088 + n0 + i) * NHID + k0 + tx] = 0.0f;
    } else if (id < 2816) {                // uk: n32 x k16
        int r = id - 2304;
        tr_tile(W_uk, NUP, g_Wu1, NDOWN, 0,    r % 32, r / 32, t, tx, ty);
    } else if (id < 3328) {                // uv
        int r = id - 2816;
        tr_tile(W_uv, NUP, g_Wu1, NDOWN, 1024, r % 32, r / 32, t, tx, ty);
    } else if (id < 3840) {                // uq
        int r = id - 3328;
        tr_tile(W_uq, NUP, g_Wu2, NDOWN, 0,    r % 32, r / 32, t, tx, ty);
    } else if (id < 4352) {                // qr
        int r = id - 3840;
        tr_tile(W_qr, NUP, g_Wu2, NDOWN, 1024, r % 32, r / 32, t, tx, ty);
    } else if (id < 6400) {                // fc: n64 x k32
        int r = id - 4352;
        tr_tile(W_fc, NHID, g_Wfc, NUP, 0, r % 64, r / 64, t, tx, ty);
    } else {                               // bias assembly: 4 blocks x 256 thr
        int base = (id - 6400) * 256 + ty * 32 + tx;
        for (int j = base; j < 5248; j += 1024) {
            if (j < 1152) {
                float v;
                if      (j < 512)  v = b_dkv[j];
                else if (j < 1024) v = b_dq[j - 512];
                else if (j < 1088) v = b_kr[j - 1024];
                else               v = 0.0f;
                g_bx[j] = v;
            } else if (j < 3200) {
                int k = j - 1152;
                g_bu1[k] = (k < 1024) ? b_uk[k] : b_uv[k - 1024];
            } else {
                int k = j - 3200;
                g_bu2[k] = (k < 1024) ? b_uq[k] : b_qr[k - 1024];
            }
        }
    }
}

// ---------------- tf32 mma.sync GEMM: C[M,·] = A[M,K](lda) @ Wt[N,K]^T + bias ------
#define STRD 36
#define BUFSZ (128*STRD)
__global__ __launch_bounds__(256) void mma_gemm(
    const float* __restrict__ A, const float* __restrict__ Wt,
    const float* __restrict__ bias, float* __restrict__ C,
    int K, int lda, int ldc)
{
    extern __shared__ float sm[];
    float* As = sm;
    float* Bs = sm + 2*BUFSZ;

    const int tid = threadIdx.x;
    const int w = tid >> 5, lane = tid & 31;
    const int g = lane >> 2, tig = lane & 3;
    const int wm = (w & 1) * 64;
    const int wn = (w >> 1) * 32;
    const int M0 = blockIdx.y * 128, N0 = blockIdx.x * 128;

    const float* Ag = A  + (size_t)M0 * lda;
    const float* Bg = Wt + (size_t)N0 * K;

    float acc[4][4][4];
    #pragma unroll
    for (int mt = 0; mt < 4; mt++)
        #pragma unroll
        for (int nt = 0; nt < 4; nt++)
            #pragma unroll
            for (int q = 0; q < 4; q++) acc[mt][nt][q] = 0.0f;

    const int row_ld = tid >> 3;
    const int kc_ld  = (tid & 7) * 4;

    {
        #pragma unroll
        for (int it = 0; it < 4; it++) {
            int row = it * 32 + row_ld;
            float4 va = *(const float4*)(Ag + (size_t)row * lda + kc_ld);
            float4 vb = *(const float4*)(Bg + (size_t)row * K + kc_ld);
            uint4 ua; ua.x = tf32r(va.x); ua.y = tf32r(va.y); ua.z = tf32r(va.z); ua.w = tf32r(va.w);
            uint4 ub; ub.x = tf32r(vb.x); ub.y = tf32r(vb.y); ub.z = tf32r(vb.z); ub.w = tf32r(vb.w);
            *(uint4*)(As + row * STRD + kc_ld) = ua;
            *(uint4*)(Bs + row * STRD + kc_ld) = ub;
        }
    }
    __syncthreads();

    const int NC = K >> 5;
    for (int ch = 0; ch < NC; ch++) {
        const int buf = ch & 1;
        const float* Ab = As + buf * BUFSZ;
        const float* Bb = Bs + buf * BUFSZ;

        float4 ra[4], rb[4];
        const bool more = (ch + 1 < NC);
        if (more) {
            const int kc0 = (ch + 1) * 32;
            #pragma unroll
            for (int it = 0; it < 4; it++) {
                int row = it * 32 + row_ld;
                ra[it] = *(const float4*)(Ag + (size_t)row * lda + kc0 + kc_ld);
                rb[it] = *(const float4*)(Bg + (size_t)row * K + kc0 + kc_ld);
            }
        }

        #pragma unroll
        for (int ks = 0; ks < 4; ks++) {
            const int k0 = ks * 8;
            uint32_t af[4][4], bf[4][2];
            #pragma unroll
            for (int mt = 0; mt < 4; mt++) {
                const float* p = Ab + (wm + mt * 16 + g) * STRD + k0 + tig;
                af[mt][0] = __float_as_uint(p[0]);
                af[mt][1] = __float_as_uint(p[8 * STRD]);
                af[mt][2] = __float_as_uint(p[4]);
                af[mt][3] = __float_as_uint(p[8 * STRD + 4]);
            }
            #pragma unroll
            for (int nt = 0; nt < 4; nt++) {
                const float* p = Bb + (wn + nt * 8 + g) * STRD + k0 + tig;
                bf[nt][0] = __float_as_uint(p[0]);
                bf[nt][1] = __float_as_uint(p[4]);
            }
            #pragma unroll
            for (int mt = 0; mt < 4; mt++)
                #pragma unroll
                for (int nt = 0; nt < 4; nt++)
                    mma_tf32_16n8k8(acc[mt][nt][0], acc[mt][nt][1],
                                    acc[mt][nt][2], acc[mt][nt][3],
                                    af[mt][0], af[mt][1], af[mt][2], af[mt][3],
                                    bf[nt][0], bf[nt][1]);
        }

        if (more) {
            float* da0 = As + (buf ^ 1) * BUFSZ;
            float* db0 = Bs + (buf ^ 1) * BUFSZ;
            #pragma unroll
            for (int it = 0; it < 4; it++) {
                int row = it * 32 + row_ld;
                uint4 ua; ua.x = tf32r(ra[it].x); ua.y = tf32r(ra[it].y);
                          ua.z = tf32r(ra[it].z); ua.w = tf32r(ra[it].w);
                uint4 ub; ub.x = tf32r(rb[it].x); ub.y = tf32r(rb[it].y);
                          ub.z = tf32r(rb[it].z); ub.w = tf32r(rb[it].w);
                *(uint4*)(da0 + row * STRD + kc_ld) = ua;
                *(uint4*)(db0 + row * STRD + kc_ld) = ub;
            }
        }
        __syncthreads();
    }

    #pragma unroll
    for (int mt = 0; mt < 4; mt++) {
        const int row = M0 + wm + mt * 16 + g;
        #pragma unroll
        for (int nt = 0; nt < 4; nt++) {
            const int col = N0 + wn + nt * 8 + 2 * tig;
            float b0 = bias[col], b1 = bias[col + 1];
            float2 o0; o0.x = acc[mt][nt][0] + b0; o0.y = acc[mt][nt][1] + b1;
            float2 o1; o1.x = acc[mt][nt][2] + b0; o1.y = acc[mt][nt][3] + b1;
            *(float2*)(C + (size_t)row * ldc + col)       = o0;
            *(float2*)(C + (size_t)(row + 8) * ldc + col) = o1;
        }
    }
}

// ---------------- fused pack: RoPE Q/K + V transpose ----------------
__global__ __launch_bounds__(256) void pack_all(
    const float* __restrict__ kcvc, const float* __restrict__ qcqr,
    const float* __restrict__ cx,
    float* __restrict__ Qn, float* __restrict__ Kn, float* __restrict__ Vt)
{
    __shared__ float t[64*65];
    const float SCALEF = 0.051776695296636886f;
    const int st = blockIdx.x;   // 64-token tiles
    const int bh = blockIdx.y;
    const int b  = bh >> 4, h = bh & 15;
    const int s0 = st * 64;
    const int tid = threadIdx.x;

    // ---- V transpose: vc = kcvc[:, 1024+h*64 ...] -> Vt[bh][dv][s] (tf32) ----
    #pragma unroll
    for (int it = 0; it < 4; it++) {
        int e = it*256 + tid;          // f4 idx 0..1023
        int sl = e >> 4, dq = (e & 15) * 4;
        float4 v = *(const float4*)(kcvc + ((size_t)(b*NS + s0 + sl))*2048 + 1024 + h*64 + dq);
        t[sl*65 + dq + 0] = v.x;
        t[sl*65 + dq + 1] = v.y;
        t[sl*65 + dq + 2] = v.z;
        t[sl*65 + dq + 3] = v.w;
    }
    __syncthreads();
    #pragma unroll
    for (int it = 0; it < 4; it++) {
        int e = it*256 + tid;
        int dv = e >> 4, sq = (e & 15) * 4;
        uint4 o;
        o.x = tf32r(t[(sq+0)*65 + dv]);
        o.y = tf32r(t[(sq+1)*65 + dv]);
        o.z = tf32r(t[(sq+2)*65 + dv]);
        o.w = tf32r(t[(sq+3)*65 + dv]);
        *(uint4*)(Vt + ((size_t)bh*64 + dv)*NS + s0 + sq) = o;
    }

    // ---- Q/K rope + pack (tf32; Q pre-scaled) ----
    float* Qo = Qn + ((size_t)bh*NS + s0) * 128;
    float* Ko = Kn + ((size_t)bh*NS + s0) * 128;
    for (int it = 0; it < 32; it++) {
        int e = it*256 + tid;          // 0..8191
        int sl = e >> 7, d = e & 127;
        int s = s0 + sl;
        int row = b*NS + s;
        float kval, qval;
        if (d < 64) {
            kval = kcvc[(size_t)row*2048 + h*64 + d];
            qval = qcqr[(size_t)row*2048 + h*64 + d];
        } else {
            int dd = d - 64;
            int i2 = dd & ~1;
            float fr = powf(10000.0f, -((float)i2) / 64.0f);
            float th = (float)s * fr;
            float cs, sn;
            sincosf(th, &sn, &cs);
            float kx1 = cx[(size_t)row*NX + 1024 + i2];
            float kx2 = cx[(size_t)row*NX + 1024 + i2 + 1];
            float qx1 = qcqr[(size_t)row*2048 + 1024 + h*64 + i2];
            float qx2 = qcqr[(size_t)row*2048 + 1024 + h*64 + i2 + 1];
            if (dd & 1) { kval = kx2*cs + kx1*sn; qval = qx2*cs + qx1*sn; }
            else        { kval = kx1*cs - kx2*sn; qval = qx1*cs - qx2*sn; }
        }
        Ko[e] = __uint_as_float(tf32r(kval));
        Qo[e] = __uint_as_float(tf32r(qval * SCALEF));
    }
}

// ---------------- tf32 mma flash attention, double-buffered ----------------
#define KSTR 132
#define VSTR 68
#define PSTR 68
__global__ __launch_bounds__(256) void attn_mma(
    const float* __restrict__ Qn, const float* __restrict__ Kn,
    const float* __restrict__ Vt, float* __restrict__ O)
{
    extern __shared__ float sm[];
    float* Kb0 = sm;
    float* Kb1 = sm + 8448;
    float* Vb0 = sm + 16896;
    float* Vb1 = sm + 16896 + 4352;
    float* Ps  = sm + 25600;

    const int tid = threadIdx.x;
    const int w = tid >> 5, lane = tid & 31;
    const int g = lane >> 2, tig = lane & 3;
    const int qt = (int)gridDim.x - 1 - (int)blockIdx.x;   // big tiles first
    const int bh = blockIdx.y;
    const int b = bh >> 4, h = bh & 15;
    const int q0 = qt * 128;
    const int rowbase = q0 + w * 16;

    const float* KgB = Kn + (size_t)bh * NS * 128;
    const float* VgB = Vt + (size_t)bh * 64 * NS;

    uint32_t qa[16][4];
    {
        const int qr0 = min(rowbase + g,     NS - 1);
        const int qr1 = min(rowbase + g + 8, NS - 1);
        const float* Qg  = Qn + ((size_t)bh * NS + qr0) * 128;
        const float* Qg8 = Qn + ((size_t)bh * NS + qr1) * 128;
        #pragma unroll
        for (int ks = 0; ks < 16; ks++) {
            qa[ks][0] = __float_as_uint(Qg [8*ks + tig]);
            qa[ks][1] = __float_as_uint(Qg8[8*ks + tig]);
            qa[ks][2] = __float_as_uint(Qg [8*ks + tig + 4]);
            qa[ks][3] = __float_as_uint(Qg8[8*ks + tig + 4]);
        }
    }

    float m0 = -1e30f, m1 = -1e30f, l0 = 0.0f, l1 = 0.0f;
    float of[8][4];
    #pragma unroll
    for (int nf = 0; nf < 8; nf++)
        #pragma unroll
        for (int c = 0; c < 4; c++) of[nf][c] = 0.0f;

    float* Pw = Ps + w * 16 * PSTR;
    const int nkt = 2*qt + 2;

    {
        #pragma unroll
        for (int it = 0; it < 8; it++) {
            int e = it*256 + tid;
            int key = e >> 5, dq = (e & 31) * 4;
            *(float4*)(Kb0 + key*KSTR + dq) = *(const float4*)(KgB + (size_t)key*128 + dq);
        }
        #pragma unroll
        for (int it = 0; it < 4; it++) {
            int e = it*256 + tid;
            int dv = e >> 4, kq = (e & 15) * 4;
            *(float4*)(Vb0 + dv*VSTR + kq) = *(const float4*)(VgB + (size_t)dv*NS + kq);
        }
    }
    __syncthreads();

    for (int kt = 0; kt < nkt; kt++) {
        const int cur = kt & 1;
        const int k0g = kt * 64;
        const float* Kbc = cur ? Kb1 : Kb0;
        const float* Vbc = cur ? Vb1 : Vb0;
        float* Kbn = cur ? Kb0 : Kb1;
        float* Vbn = cur ? Vb0 : Vb1;

        float4 rk[8], rv[4];
        const bool more = (kt + 1 < nkt);
        if (more) {
            const int kn0 = k0g + 64;
            #pragma unroll
            for (int it = 0; it < 8; it++) {
                int e = it*256 + tid;
                int key = e >> 5, dq = (e & 31) * 4;
                int krow = min(kn0 + key, NS - 1);
                rk[it] = *(const float4*)(KgB + (size_t)krow*128 + dq);
            }
            #pragma unroll
            for (int it = 0; it < 4; it++) {
                int e = it*256 + tid;
                int dv = e >> 4, kq = (e & 15) * 4;
                int kcol = min(kn0 + kq, NS - 4);
                rv[it] = *(const float4*)(VgB + (size_t)dv*NS + kcol);
            }
        }

        float sf[8][4];
        #pragma unroll
        for (int nf = 0; nf < 8; nf++)
            #pragma unroll
            for (int c = 0; c < 4; c++) sf[nf][c] = 0.0f;

        #pragma unroll
        for (int ks = 0; ks < 16; ks++) {
            #pragma unroll
            for (int nf = 0; nf < 8; nf++) {
                const float* bp = Kbc + (nf*8 + g)*KSTR + 8*ks + tig;
                uint32_t b0 = __float_as_uint(bp[0]);
                uint32_t b1 = __float_as_uint(bp[4]);
                mma_tf32_16n8k8(sf[nf][0], sf[nf][1], sf[nf][2], sf[nf][3],
                                qa[ks][0], qa[ks][1], qa[ks][2], qa[ks][3], b0, b1);
            }
        }

        const int row0 = rowbase + g, row1 = row0 + 8;
        if (k0g + 63 > rowbase) {
            #pragma unroll
            for (int nf = 0; nf < 8; nf++) {
                int col = k0g + nf*8 + 2*tig;
                if (col     > row0) sf[nf][0] = -1e9f;
                if (col + 1 > row0) sf[nf][1] = -1e9f;
                if (col     > row1) sf[nf][2] = -1e9f;
                if (col + 1 > row1) sf[nf][3] = -1e9f;
            }
        }
        float mx0 = -1e30f, mx1 = -1e30f;
        #pragma unroll
        for (int nf = 0; nf < 8; nf++) {
            mx0 = fmaxf(mx0, fmaxf(sf[nf][0], sf[nf][1]));
            mx1 = fmaxf(mx1, fmaxf(sf[nf][2], sf[nf][3]));
        }
        mx0 = fmaxf(mx0, __shfl_xor_sync(0xffffffffu, mx0, 1));
        mx0 = fmaxf(mx0, __shfl_xor_sync(0xffffffffu, mx0, 2));
        mx1 = fmaxf(mx1, __shfl_xor_sync(0xffffffffu, mx1, 1));
        mx1 = fmaxf(mx1, __shfl_xor_sync(0xffffffffu, mx1, 2));
        float mn0 = fmaxf(m0, mx0), mn1 = fmaxf(m1, mx1);
        float cr0 = __expf(m0 - mn0), cr1 = __expf(m1 - mn1);
        float ps0 = 0.0f, ps1 = 0.0f;
        #pragma unroll
        for (int nf = 0; nf < 8; nf++) {
            sf[nf][0] = __expf(sf[nf][0] - mn0);
            sf[nf][1] = __expf(sf[nf][1] - mn0);
            sf[nf][2] = __expf(sf[nf][2] - mn1);
            sf[nf][3] = __expf(sf[nf][3] - mn1);
            ps0 += sf[nf][0] + sf[nf][1];
            ps1 += sf[nf][2] + sf[nf][3];
        }
        ps0 += __shfl_xor_sync(0xffffffffu, ps0, 1);
        ps0 += __shfl_xor_sync(0xffffffffu, ps0, 2);
        ps1 += __shfl_xor_sync(0xffffffffu, ps1, 1);
        ps1 += __shfl_xor_sync(0xffffffffu, ps1, 2);
        l0 = l0*cr0 + ps0;  m0 = mn0;
        l1 = l1*cr1 + ps1;  m1 = mn1;

        #pragma unroll
        for (int nf = 0; nf < 8; nf++) {
            of[nf][0] *= cr0; of[nf][1] *= cr0;
            of[nf][2] *= cr1; of[nf][3] *= cr1;
            int col = nf*8 + 2*tig;
            Pw[g*PSTR + col]           = __uint_as_float(tf32r(sf[nf][0]));
            Pw[g*PSTR + col + 1]       = __uint_as_float(tf32r(sf[nf][1]));
            Pw[(g+8)*PSTR + col]       = __uint_as_float(tf32r(sf[nf][2]));
            Pw[(g+8)*PSTR + col + 1]   = __uint_as_float(tf32r(sf[nf][3]));
        }
        __syncwarp();

        if (more) {
            #pragma unroll
            for (int it = 0; it < 8; it++) {
                int e = it*256 + tid;
                int key = e >> 5, dq = (e & 31) * 4;
                *(float4*)(Kbn + key*KSTR + dq) = rk[it];
            }
            #pragma unroll
            for (int it = 0; it < 4; it++) {
                int e = it*256 + tid;
                int dv = e >> 4, kq = (e & 15) * 4;
                *(float4*)(Vbn + dv*VSTR + kq) = rv[it];
            }
        }

        #pragma unroll
        for (int ks = 0; ks < 8; ks++) {
            uint32_t a0 = __float_as_uint(Pw[g*PSTR + 8*ks + tig]);
            uint32_t a1 = __float_as_uint(Pw[(g+8)*PSTR + 8*ks + tig]);
            uint32_t a2 = __float_as_uint(Pw[g*PSTR + 8*ks + tig + 4]);
            uint32_t a3 = __float_as_uint(Pw[(g+8)*PSTR + 8*ks + tig + 4]);
            #pragma unroll
            for (int nf = 0; nf < 8; nf++) {
                const float* vp = Vbc + (nf*8 + g)*VSTR + 8*ks + tig;
                uint32_t b0 = __float_as_uint(vp[0]);
                uint32_t b1 = __float_as_uint(vp[4]);
                mma_tf32_16n8k8(of[nf][0], of[nf][1], of[nf][2], of[nf][3],
                                a0, a1, a2, a3, b0, b1);
            }
        }
        __syncthreads();
    }

    const float inv0 = 1.0f / l0, inv1 = 1.0f / l1;
    const int tok0 = b*NS + rowbase + g;
    #pragma unroll
    for (int nf = 0; nf < 8; nf++) {
        int col = h*64 + nf*8 + 2*tig;
        float2 o0; o0.x = of[nf][0]*inv0; o0.y = of[nf][1]*inv0;
        float2 o1; o1.x = of[nf][2]*inv1; o1.y = of[nf][3]*inv1;
        *(float2*)(O + (size_t)tok0 * NUP + col)     = o0;
        *(float2*)(O + (size_t)(tok0+8) * NUP + col) = o1;
    }
}

// ---------------- host launcher ----------------
extern "C" void kernel_launch(void* const* d_in, const int* in_sizes, int n_in,
                              void* d_out, int out_size)
{
    (void)in_sizes; (void)n_in; (void)out_size;
    const float* X     = (const float*)d_in[0];
    const float* W_dkv = (const float*)d_in[2];
    const float* b_dkv = (const float*)d_in[3];
    const float* W_dq  = (const float*)d_in[4];
    const float* b_dq  = (const float*)d_in[5];
    const float* W_uk  = (const float*)d_in[6];
    const float* b_uk  = (const float*)d_in[7];
    const float* W_uv  = (const float*)d_in[8];
    const float* b_uv  = (const float*)d_in[9];
    const float* W_uq  = (const float*)d_in[10];
    const float* b_uq  = (const float*)d_in[11];
    const float* W_qr  = (const float*)d_in[12];
    const float* b_qr  = (const float*)d_in[13];
    const float* W_kr  = (const float*)d_in[14];
    const float* b_kr  = (const float*)d_in[15];
    const float* W_fc  = (const float*)d_in[16];
    const float* b_fc  = (const float*)d_in[17];
    float* out = (float*)d_out;

    float *cx, *kcvc, *qcqr, *Qn, *Kn, *Vt, *ao;
    float *Wx, *Wu1, *Wu2, *Wfc, *bx, *bu1, *bu2;
    cudaGetSymbolAddress((void**)&cx,   g_cx);
    cudaGetSymbolAddress((void**)&kcvc, g_kcvc);
    cudaGetSymbolAddress((void**)&qcqr, g_qcqr);
    cudaGetSymbolAddress((void**)&Qn,   g_Qn);
    cudaGetSymbolAddress((void**)&Kn,   g_Kn);
    cudaGetSymbolAddress((void**)&Vt,   g_Vt);
    cudaGetSymbolAddress((void**)&ao,   g_ao);
    cudaGetSymbolAddress((void**)&Wx,   g_Wx);
    cudaGetSymbolAddress((void**)&Wu1,  g_Wu1);
    cudaGetSymbolAddress((void**)&Wu2,  g_Wu2);
    cudaGetSymbolAddress((void**)&Wfc,  g_Wfc);
    cudaGetSymbolAddress((void**)&bx,   g_bx);
    cudaGetSymbolAddress((void**)&bu1,  g_bu1);
    cudaGetSymbolAddress((void**)&bu2,  g_bu2);

    // [0] weight prep (transposes + bias assembly)
    wprep<<<6404, dim3(32, 8)>>>(W_dkv, W_dq, W_kr, W_uk, W_uv, W_uq, W_qr, W_fc,
                                 b_dkv, b_dq, b_kr, b_uk, b_uv, b_uq, b_qr);

    const int GSM = 4 * BUFSZ * 4;
    cudaFuncSetAttribute(mma_gemm, cudaFuncAttributeMaxDynamicSharedMemorySize, GSM);

    // [1] X projections: cx = X @ [Wdkv|Wdq|Wkr|pad] + bx   (N=1152)
    mma_gemm<<<dim3(NX/128, NBS/128), 256, GSM>>>(X,  Wx,  bx,  cx,   NHID, NHID, NX);
    // [2] up1: kcvc = ckv @ [Wuk|Wuv] + bu1                 (N=2048)
    mma_gemm<<<dim3(16, NBS/128), 256, GSM>>>(cx,       Wu1, bu1, kcvc, NDOWN, NX, 2048);
    // [3] up2: qcqr = cq @ [Wuq|Wqr] + bu2                  (N=2048)
    mma_gemm<<<dim3(16, NBS/128), 256, GSM>>>(cx + 512, Wu2, bu2, qcqr, NDOWN, NX, 2048);

    // [4] fused pack: rope Q/K + V transpose
    pack_all<<<dim3(32, 64), 256>>>(kcvc, qcqr, cx, Qn, Kn, Vt);

    // [5] attention (profiled by ncu -s 5 -c 1)
    const int ASM = 34304 * 4;   // 137216 bytes
    cudaFuncSetAttribute(attn_mma, cudaFuncAttributeMaxDynamicSharedMemorySize, ASM);
    attn_mma<<<dim3(16, 64), 256, ASM>>>(Qn, Kn, Vt, ao);

    // [6] final projection
    mma_gemm<<<dim3(16, NBS/128), 256, GSM>>>(ao, Wfc, b_fc, out, NUP, NUP, 2048);
}

// round 9
// speedup vs baseline: 3.8064x; 1.2022x over previous
#include <cuda_runtime.h>
#include <math.h>
#include <stdint.h>

// Problem constants
#define NB    4
#define NS    2048
#define NHID  2048
#define NDOWN 512
#define NUP   1024
#define NH    16
#define NROPE 64
#define NBS   (NB*NS)          // 8192 tokens
#define NX    1152             // combined X-proj output width: 512+512+64+64pad

// ---------------- scratch (device globals) ----------------
__device__ float g_Xr  [NBS*NHID];      // X rounded to tf32
__device__ float g_cx  [NBS*NX];        // [tok][dkv|dq|kr|pad]   (tf32)
__device__ float g_kcvc[NBS*2048];      // [tok][kc|vc]           (tf32)
__device__ float g_qcqr[NBS*2048];      // [tok][qc|qr]           (tf32)
__device__ float g_Qn [NB*NH*NS*128];   // [bh][s][128] tf32, pre-scaled
__device__ float g_Kn [NB*NH*NS*128];   // [bh][s][128] tf32
__device__ float g_Vt [NB*NH*64*NS];    // [bh][dv][s]  tf32
__device__ float g_ao [NBS*NUP];        // attention out (tf32)

__device__ float g_Wx [NX*NHID];        // tf32
__device__ float g_Wu1[2048*NDOWN];     // tf32
__device__ float g_Wu2[2048*NDOWN];     // tf32
__device__ float g_Wfc[NHID*NUP];       // tf32
__device__ float g_bx [NX];
__device__ float g_bu1[2048];
__device__ float g_bu2[2048];

// ---------------- helpers ----------------
__device__ __forceinline__ uint32_t tf32r(float x) {
    uint32_t u;
    asm("cvt.rna.tf32.f32 %0, %1;" : "=r"(u) : "f"(x));
    return u;
}
__device__ __forceinline__ void mma_tf32_16n8k8(
    float& c0, float& c1, float& c2, float& c3,
    uint32_t a0, uint32_t a1, uint32_t a2, uint32_t a3,
    uint32_t b0, uint32_t b1)
{
    asm volatile(
        "mma.sync.aligned.m16n8k8.row.col.f32.tf32.tf32.f32 "
        "{%0,%1,%2,%3}, {%4,%5,%6,%7}, {%8,%9}, {%0,%1,%2,%3};"
        : "+f"(c0), "+f"(c1), "+f"(c2), "+f"(c3)
        : "r"(a0), "r"(a1), "r"(a2), "r"(a3), "r"(b0), "r"(b1));
}
__device__ __forceinline__ void cp16(uint32_t saddr, const void* gptr) {
    asm volatile("cp.async.cg.shared.global [%0], [%1], 16;"
                 :: "r"(saddr), "l"(gptr) : "memory");
}
#define CP_COMMIT() asm volatile("cp.async.commit_group;" ::: "memory")
#define CP_WAIT0()  asm volatile("cp.async.wait_group 0;" ::: "memory")

// ---------------- fused weight prep: transposes (tf32) + bias + X cvt ----------------
__device__ __forceinline__ void tr_tile(
    const float* __restrict__ W, int srcN,
    float* __restrict__ dst, int dstK, int rowbase,
    int nt, int kt, float (*t)[33], int tx, int ty)
{
    const int n0 = nt * 32, k0 = kt * 32;
    #pragma unroll
    for (int i = ty; i < 32; i += 8)
        t[i][tx] = W[(size_t)(k0 + i) * srcN + n0 + tx];
    __syncthreads();
    #pragma unroll
    for (int i = ty; i < 32; i += 8)
        dst[(size_t)(rowbase + n0 + i) * dstK + k0 + tx] = __uint_as_float(tf32r(t[tx][i]));
}

__global__ __launch_bounds__(256) void wprep(
    const float* __restrict__ X,
    const float* __restrict__ W_dkv, const float* __restrict__ W_dq,
    const float* __restrict__ W_kr,  const float* __restrict__ W_uk,
    const float* __restrict__ W_uv,  const float* __restrict__ W_uq,
    const float* __restrict__ W_qr,  const float* __restrict__ W_fc,
    const float* __restrict__ b_dkv, const float* __restrict__ b_dq,
    const float* __restrict__ b_kr,  const float* __restrict__ b_uk,
    const float* __restrict__ b_uv,  const float* __restrict__ b_uq,
    const float* __restrict__ b_qr)
{
    __shared__ float t[32][33];
    const int tx = threadIdx.x, ty = threadIdx.y;
    const int id = blockIdx.x;

    if (id < 1024) {
        tr_tile(W_dkv, NDOWN, g_Wx, NHID, 0,    id % 16, id / 16, t, tx, ty);
    } else if (id < 2048) {
        int r = id - 1024;
        tr_tile(W_dq,  NDOWN, g_Wx, NHID, 512,  r % 16, r / 16, t, tx, ty);
    } else if (id < 2176) {
        int r = id - 2048;
        tr_tile(W_kr,  NROPE, g_Wx, NHID, 1024, r % 2, r / 2, t, tx, ty);
    } else if (id < 2304) {
        int r = id - 2176;
        int n0 = (r % 2) * 32, k0 = (r / 2) * 32;
        #pragma unroll
        for (int i = ty; i < 32; i += 8)
            g_Wx[(size_t)(1088 + n0 + i) * NHID + k0 + tx] = 0.0f;
    } else if (id < 2816) {
        int r = id - 2304;
        tr_tile(W_uk, NUP, g_Wu1, NDOWN, 0,    r % 32, r / 32, t, tx, ty);
    } else if (id < 3328) {
        int r = id - 2816;
        tr_tile(W_uv, NUP, g_Wu1, NDOWN, 1024, r % 32, r / 32, t, tx, ty);
    } else if (id < 3840) {
        int r = id - 3328;
        tr_tile(W_uq, NUP, g_Wu2, NDOWN, 0,    r % 32, r / 32, t, tx, ty);
    } else if (id < 4352) {
        int r = id - 3840;
        tr_tile(W_qr, NUP, g_Wu2, NDOWN, 1024, r % 32, r / 32, t, tx, ty);
    } else if (id < 6400) {
        int r = id - 4352;
        tr_tile(W_fc, NHID, g_Wfc, NUP, 0, r % 64, r / 64, t, tx, ty);
    } else if (id < 6404) {
        int base = (id - 6400) * 256 + ty * 32 + tx;
        for (int j = base; j < 5248; j += 1024) {
            if (j < 1152) {
                float v;
                if      (j < 512)  v = b_dkv[j];
                else if (j < 1024) v = b_dq[j - 512];
                else if (j < 1088) v = b_kr[j - 1024];
                else               v = 0.0f;
                g_bx[j] = v;
            } else if (j < 3200) {
                int k = j - 1152;
                g_bu1[k] = (k < 1024) ? b_uk[k] : b_uv[k - 1024];
            } else {
                int k = j - 3200;
                g_bu2[k] = (k < 1024) ? b_uq[k] : b_qr[k - 1024];
            }
        }
    } else {
        // X -> tf32-rounded g_Xr. 1024 blocks x 256 thr x 16 f4 = 4M f4.
        const int tid = ty * 32 + tx;
        size_t base = ((size_t)(id - 6404) * 4096 + tid) * 4;
        #pragma unroll
        for (int it = 0; it < 16; it++) {
            size_t e4 = base + (size_t)it * 1024;   // float offset
            float4 v = *(const float4*)(X + e4);
            uint4 u; u.x = tf32r(v.x); u.y = tf32r(v.y); u.z = tf32r(v.z); u.w = tf32r(v.w);
            *(uint4*)(g_Xr + e4) = u;
        }
    }
}

// ---------------- tf32 mma.sync GEMM (cp.async, 2 CTA/SM) ----------------
// C[M,·] = A[M,K](lda) @ Wt[N,K]^T + bias.  Inputs pre-rounded to tf32.
#define STRD 36
#define BUFSZ (128*STRD)
template<bool RND>
__global__ __launch_bounds__(256, 2) void mma_gemm(
    const float* __restrict__ A, const float* __restrict__ Wt,
    const float* __restrict__ bias, float* __restrict__ C,
    int K, int lda, int ldc)
{
    extern __shared__ float sm[];
    float* As = sm;
    float* Bs = sm + 2*BUFSZ;
    const uint32_t AsU = (uint32_t)__cvta_generic_to_shared(As);
    const uint32_t BsU = (uint32_t)__cvta_generic_to_shared(Bs);

    const int tid = threadIdx.x;
    const int w = tid >> 5, lane = tid & 31;
    const int g = lane >> 2, tig = lane & 3;
    const int wm = (w & 1) * 64;
    const int wn = (w >> 1) * 32;
    const int M0 = blockIdx.y * 128, N0 = blockIdx.x * 128;

    const float* Ag = A  + (size_t)M0 * lda;
    const float* Bg = Wt + (size_t)N0 * K;

    float acc[4][4][4];
    #pragma unroll
    for (int mt = 0; mt < 4; mt++)
        #pragma unroll
        for (int nt = 0; nt < 4; nt++)
            #pragma unroll
            for (int q = 0; q < 4; q++) acc[mt][nt][q] = 0.0f;

    const int row_ld = tid >> 3;
    const int kc_ld  = (tid & 7) * 4;

    // fill buffer 0 (chunk 0)
    {
        #pragma unroll
        for (int it = 0; it < 4; it++) {
            int row = it * 32 + row_ld;
            cp16(AsU + (uint32_t)(row * STRD + kc_ld) * 4, Ag + (size_t)row * lda + kc_ld);
            cp16(BsU + (uint32_t)(row * STRD + kc_ld) * 4, Bg + (size_t)row * K   + kc_ld);
        }
        CP_COMMIT();
        CP_WAIT0();
    }
    __syncthreads();

    const int NC = K >> 5;
    for (int ch = 0; ch < NC; ch++) {
        const int buf = ch & 1;
        const float* Ab = As + buf * BUFSZ;
        const float* Bb = Bs + buf * BUFSZ;

        const bool more = (ch + 1 < NC);
        if (more) {
            const int kc0 = (ch + 1) * 32;
            const uint32_t au = AsU + (uint32_t)(buf ^ 1) * (BUFSZ * 4);
            const uint32_t bu = BsU + (uint32_t)(buf ^ 1) * (BUFSZ * 4);
            #pragma unroll
            for (int it = 0; it < 4; it++) {
                int row = it * 32 + row_ld;
                cp16(au + (uint32_t)(row * STRD + kc_ld) * 4, Ag + (size_t)row * lda + kc0 + kc_ld);
                cp16(bu + (uint32_t)(row * STRD + kc_ld) * 4, Bg + (size_t)row * K   + kc0 + kc_ld);
            }
            CP_COMMIT();
        }

        #pragma unroll
        for (int ks = 0; ks < 4; ks++) {
            const int k0 = ks * 8;
            uint32_t af[4][4], bf[4][2];
            #pragma unroll
            for (int mt = 0; mt < 4; mt++) {
                const float* p = Ab + (wm + mt * 16 + g) * STRD + k0 + tig;
                af[mt][0] = __float_as_uint(p[0]);
                af[mt][1] = __float_as_uint(p[8 * STRD]);
                af[mt][2] = __float_as_uint(p[4]);
                af[mt][3] = __float_as_uint(p[8 * STRD + 4]);
            }
            #pragma unroll
            for (int nt = 0; nt < 4; nt++) {
                const float* p = Bb + (wn + nt * 8 + g) * STRD + k0 + tig;
                bf[nt][0] = __float_as_uint(p[0]);
                bf[nt][1] = __float_as_uint(p[4]);
            }
            #pragma unroll
            for (int mt = 0; mt < 4; mt++)
                #pragma unroll
                for (int nt = 0; nt < 4; nt++)
                    mma_tf32_16n8k8(acc[mt][nt][0], acc[mt][nt][1],
                                    acc[mt][nt][2], acc[mt][nt][3],
                                    af[mt][0], af[mt][1], af[mt][2], af[mt][3],
                                    bf[nt][0], bf[nt][1]);
        }

        if (more) CP_WAIT0();
        __syncthreads();
    }

    #pragma unroll
    for (int mt = 0; mt < 4; mt++) {
        const int row = M0 + wm + mt * 16 + g;
        #pragma unroll
        for (int nt = 0; nt < 4; nt++) {
            const int col = N0 + wn + nt * 8 + 2 * tig;
            float b0 = bias[col], b1 = bias[col + 1];
            float v00 = acc[mt][nt][0] + b0, v01 = acc[mt][nt][1] + b1;
            float v10 = acc[mt][nt][2] + b0, v11 = acc[mt][nt][3] + b1;
            if (RND) {
                v00 = __uint_as_float(tf32r(v00)); v01 = __uint_as_float(tf32r(v01));
                v10 = __uint_as_float(tf32r(v10)); v11 = __uint_as_float(tf32r(v11));
            }
            float2 o0; o0.x = v00; o0.y = v01;
            float2 o1; o1.x = v10; o1.y = v11;
            *(float2*)(C + (size_t)row * ldc + col)       = o0;
            *(float2*)(C + (size_t)(row + 8) * ldc + col) = o1;
        }
    }
}

// ---------------- fused pack: RoPE Q/K + V transpose ----------------
__global__ __launch_bounds__(256) void pack_all(
    const float* __restrict__ kcvc, const float* __restrict__ qcqr,
    const float* __restrict__ cx,
    float* __restrict__ Qn, float* __restrict__ Kn, float* __restrict__ Vt)
{
    __shared__ float t[64*65];
    const float SCALEF = 0.051776695296636886f;
    const int st = blockIdx.x;
    const int bh = blockIdx.y;
    const int b  = bh >> 4, h = bh & 15;
    const int s0 = st * 64;
    const int tid = threadIdx.x;

    #pragma unroll
    for (int it = 0; it < 4; it++) {
        int e = it*256 + tid;
        int sl = e >> 4, dq = (e & 15) * 4;
        float4 v = *(const float4*)(kcvc + ((size_t)(b*NS + s0 + sl))*2048 + 1024 + h*64 + dq);
        t[sl*65 + dq + 0] = v.x;
        t[sl*65 + dq + 1] = v.y;
        t[sl*65 + dq + 2] = v.z;
        t[sl*65 + dq + 3] = v.w;
    }
    __syncthreads();
    #pragma unroll
    for (int it = 0; it < 4; it++) {
        int e = it*256 + tid;
        int dv = e >> 4, sq = (e & 15) * 4;
        float4 o;
        o.x = t[(sq+0)*65 + dv];
        o.y = t[(sq+1)*65 + dv];
        o.z = t[(sq+2)*65 + dv];
        o.w = t[(sq+3)*65 + dv];
        *(float4*)(Vt + ((size_t)bh*64 + dv)*NS + s0 + sq) = o;
    }

    float* Qo = Qn + ((size_t)bh*NS + s0) * 128;
    float* Ko = Kn + ((size_t)bh*NS + s0) * 128;
    for (int it = 0; it < 32; it++) {
        int e = it*256 + tid;
        int sl = e >> 7, d = e & 127;
        int s = s0 + sl;
        int row = b*NS + s;
        float kval, qval;
        if (d < 64) {
            kval = kcvc[(size_t)row*2048 + h*64 + d];
            qval = qcqr[(size_t)row*2048 + h*64 + d];
        } else {
            int dd = d - 64;
            int i2 = dd & ~1;
            float fr = powf(10000.0f, -((float)i2) / 64.0f);
            float th = (float)s * fr;
            float cs, sn;
            sincosf(th, &sn, &cs);
            float kx1 = cx[(size_t)row*NX + 1024 + i2];
            float kx2 = cx[(size_t)row*NX + 1024 + i2 + 1];
            float qx1 = qcqr[(size_t)row*2048 + 1024 + h*64 + i2];
            float qx2 = qcqr[(size_t)row*2048 + 1024 + h*64 + i2 + 1];
            if (dd & 1) { kval = kx2*cs + kx1*sn; qval = qx2*cs + qx1*sn; }
            else        { kval = kx1*cs - kx2*sn; qval = qx1*cs - qx2*sn; }
        }
        Ko[e] = __uint_as_float(tf32r(kval));
        Qo[e] = __uint_as_float(tf32r(qval * SCALEF));
    }
}

// ---------------- tf32 mma flash attention, double-buffered via cp.async ----------------
#define KSTR 132
#define VSTR 68
#define PSTR 68
__global__ __launch_bounds__(256) void attn_mma(
    const float* __restrict__ Qn, const float* __restrict__ Kn,
    const float* __restrict__ Vt, float* __restrict__ O)
{
    extern __shared__ float sm[];
    float* Kb0 = sm;
    float* Kb1 = sm + 8448;
    float* Vb0 = sm + 16896;
    float* Vb1 = sm + 16896 + 4352;
    float* Ps  = sm + 25600;
    const uint32_t smU = (uint32_t)__cvta_generic_to_shared(sm);

    const int tid = threadIdx.x;
    const int w = tid >> 5, lane = tid & 31;
    const int g = lane >> 2, tig = lane & 3;
    const int qt = (int)gridDim.x - 1 - (int)blockIdx.x;
    const int bh = blockIdx.y;
    const int b = bh >> 4, h = bh & 15;
    const int q0 = qt * 128;
    const int rowbase = q0 + w * 16;

    const float* KgB = Kn + (size_t)bh * NS * 128;
    const float* VgB = Vt + (size_t)bh * 64 * NS;

    uint32_t qa[16][4];
    {
        const int qr0 = min(rowbase + g,     NS - 1);
        const int qr1 = min(rowbase + g + 8, NS - 1);
        const float* Qg  = Qn + ((size_t)bh * NS + qr0) * 128;
        const float* Qg8 = Qn + ((size_t)bh * NS + qr1) * 128;
        #pragma unroll
        for (int ks = 0; ks < 16; ks++) {
            qa[ks][0] = __float_as_uint(Qg [8*ks + tig]);
            qa[ks][1] = __float_as_uint(Qg8[8*ks + tig]);
            qa[ks][2] = __float_as_uint(Qg [8*ks + tig + 4]);
            qa[ks][3] = __float_as_uint(Qg8[8*ks + tig + 4]);
        }
    }

    float m0 = -1e30f, m1 = -1e30f, l0 = 0.0f, l1 = 0.0f;
    float of[8][4];
    #pragma unroll
    for (int nf = 0; nf < 8; nf++)
        #pragma unroll
        for (int c = 0; c < 4; c++) of[nf][c] = 0.0f;

    float* Pw = Ps + w * 16 * PSTR;
    const int nkt = 2*qt + 2;

    // K/V fill helper offsets (float4-granular, 256 threads)
    const int k_key = tid >> 3;            // wrong granularity placeholder (unused)
    (void)k_key;

    // prologue: cp.async fill buffer 0
    {
        #pragma unroll
        for (int it = 0; it < 8; it++) {
            int e = it*256 + tid;
            int key = e >> 5, dq = (e & 31) * 4;
            cp16(smU + (uint32_t)(key*KSTR + dq) * 4, KgB + (size_t)key*128 + dq);
        }
        #pragma unroll
        for (int it = 0; it < 4; it++) {
            int e = it*256 + tid;
            int dv = e >> 4, kq = (e & 15) * 4;
            cp16(smU + (uint32_t)(16896 + dv*VSTR + kq) * 4, VgB + (size_t)dv*NS + kq);
        }
        CP_COMMIT();
        CP_WAIT0();
    }
    __syncthreads();

    for (int kt = 0; kt < nkt; kt++) {
        const int cur = kt & 1;
        const int k0g = kt * 64;
        const float* Kbc = cur ? Kb1 : Kb0;
        const float* Vbc = cur ? Vb1 : Vb0;

        const bool more = (kt + 1 < nkt);
        if (more) {
            const int kn0 = k0g + 64;
            const uint32_t kbU = smU + (uint32_t)((cur ^ 1) ? 8448*4 : 0);
            const uint32_t vbU = smU + (uint32_t)(16896 + ((cur ^ 1) ? 4352 : 0)) * 4;
            #pragma unroll
            for (int it = 0; it < 8; it++) {
                int e = it*256 + tid;
                int key = e >> 5, dq = (e & 31) * 4;
                int krow = min(kn0 + key, NS - 1);
                cp16(kbU + (uint32_t)(key*KSTR + dq) * 4, KgB + (size_t)krow*128 + dq);
            }
            #pragma unroll
            for (int it = 0; it < 4; it++) {
                int e = it*256 + tid;
                int dv = e >> 4, kq = (e & 15) * 4;
                int kcol = min(kn0 + kq, NS - 4);
                cp16(vbU + (uint32_t)(dv*VSTR + kq) * 4, VgB + (size_t)dv*NS + kcol);
            }
            CP_COMMIT();
        }

        float sf[8][4];
        #pragma unroll
        for (int nf = 0; nf < 8; nf++)
            #pragma unroll
            for (int c = 0; c < 4; c++) sf[nf][c] = 0.0f;

        #pragma unroll
        for (int ks = 0; ks < 16; ks++) {
            #pragma unroll
            for (int nf = 0; nf < 8; nf++) {
                const float* bp = Kbc + (nf*8 + g)*KSTR + 8*ks + tig;
                uint32_t b0 = __float_as_uint(bp[0]);
                uint32_t b1 = __float_as_uint(bp[4]);
                mma_tf32_16n8k8(sf[nf][0], sf[nf][1], sf[nf][2], sf[nf][3],
                                qa[ks][0], qa[ks][1], qa[ks][2], qa[ks][3], b0, b1);
            }
        }

        const int row0 = rowbase + g, row1 = row0 + 8;
        if (k0g + 63 > rowbase) {
            #pragma unroll
            for (int nf = 0; nf < 8; nf++) {
                int col = k0g + nf*8 + 2*tig;
                if (col     > row0) sf[nf][0] = -1e9f;
                if (col + 1 > row0) sf[nf][1] = -1e9f;
                if (col     > row1) sf[nf][2] = -1e9f;
                if (col + 1 > row1) sf[nf][3] = -1e9f;
            }
        }
        float mx0 = -1e30f, mx1 = -1e30f;
        #pragma unroll
        for (int nf = 0; nf < 8; nf++) {
            mx0 = fmaxf(mx0, fmaxf(sf[nf][0], sf[nf][1]));
            mx1 = fmaxf(mx1, fmaxf(sf[nf][2], sf[nf][3]));
        }
        mx0 = fmaxf(mx0, __shfl_xor_sync(0xffffffffu, mx0, 1));
        mx0 = fmaxf(mx0, __shfl_xor_sync(0xffffffffu, mx0, 2));
        mx1 = fmaxf(mx1, __shfl_xor_sync(0xffffffffu, mx1, 1));
        mx1 = fmaxf(mx1, __shfl_xor_sync(0xffffffffu, mx1, 2));
        float mn0 = fmaxf(m0, mx0), mn1 = fmaxf(m1, mx1);
        float cr0 = __expf(m0 - mn0), cr1 = __expf(m1 - mn1);
        float ps0 = 0.0f, ps1 = 0.0f;
        #pragma unroll
        for (int nf = 0; nf < 8; nf++) {
            sf[nf][0] = __expf(sf[nf][0] - mn0);
            sf[nf][1] = __expf(sf[nf][1] - mn0);
            sf[nf][2] = __expf(sf[nf][2] - mn1);
            sf[nf][3] = __expf(sf[nf][3] - mn1);
            ps0 += sf[nf][0] + sf[nf][1];
            ps1 += sf[nf][2] + sf[nf][3];
        }
        ps0 += __shfl_xor_sync(0xffffffffu, ps0, 1);
        ps0 += __shfl_xor_sync(0xffffffffu, ps0, 2);
        ps1 += __shfl_xor_sync(0xffffffffu, ps1, 1);
        ps1 += __shfl_xor_sync(0xffffffffu, ps1, 2);
        l0 = l0*cr0 + ps0;  m0 = mn0;
        l1 = l1*cr1 + ps1;  m1 = mn1;

        #pragma unroll
        for (int nf = 0; nf < 8; nf++) {
            of[nf][0] *= cr0; of[nf][1] *= cr0;
            of[nf][2] *= cr1; of[nf][3] *= cr1;
            int col = nf*8 + 2*tig;
            Pw[g*PSTR + col]           = __uint_as_float(tf32r(sf[nf][0]));
            Pw[g*PSTR + col + 1]       = __uint_as_float(tf32r(sf[nf][1]));
            Pw[(g+8)*PSTR + col]       = __uint_as_float(tf32r(sf[nf][2]));
            Pw[(g+8)*PSTR + col + 1]   = __uint_as_float(tf32r(sf[nf][3]));
        }
        __syncwarp();

        #pragma unroll
        for (int ks = 0; ks < 8; ks++) {
            uint32_t a0 = __float_as_uint(Pw[g*PSTR + 8*ks + tig]);
            uint32_t a1 = __float_as_uint(Pw[(g+8)*PSTR + 8*ks + tig]);
            uint32_t a2 = __float_as_uint(Pw[g*PSTR + 8*ks + tig + 4]);
            uint32_t a3 = __float_as_uint(Pw[(g+8)*PSTR + 8*ks + tig + 4]);
            #pragma unroll
            for (int nf = 0; nf < 8; nf++) {
                const float* vp = Vbc + (nf*8 + g)*VSTR + 8*ks + tig;
                uint32_t b0 = __float_as_uint(vp[0]);
                uint32_t b1 = __float_as_uint(vp[4]);
                mma_tf32_16n8k8(of[nf][0], of[nf][1], of[nf][2], of[nf][3],
                                a0, a1, a2, a3, b0, b1);
            }
        }

        if (more) CP_WAIT0();
        __syncthreads();
    }

    const float inv0 = 1.0f / l0, inv1 = 1.0f / l1;
    const int tok0 = b*NS + rowbase + g;
    #pragma unroll
    for (int nf = 0; nf < 8; nf++) {
        int col = h*64 + nf*8 + 2*tig;
        float2 o0, o1;
        o0.x = __uint_as_float(tf32r(of[nf][0]*inv0));
        o0.y = __uint_as_float(tf32r(of[nf][1]*inv0));
        o1.x = __uint_as_float(tf32r(of[nf][2]*inv1));
        o1.y = __uint_as_float(tf32r(of[nf][3]*inv1));
        *(float2*)(O + (size_t)tok0 * NUP + col)     = o0;
        *(float2*)(O + (size_t)(tok0+8) * NUP + col) = o1;
    }
}

// ---------------- host launcher ----------------
extern "C" void kernel_launch(void* const* d_in, const int* in_sizes, int n_in,
                              void* d_out, int out_size)
{
    (void)in_sizes; (void)n_in; (void)out_size;
    const float* X     = (const float*)d_in[0];
    const float* W_dkv = (const float*)d_in[2];
    const float* b_dkv = (const float*)d_in[3];
    const float* W_dq  = (const float*)d_in[4];
    const float* b_dq  = (const float*)d_in[5];
    const float* W_uk  = (const float*)d_in[6];
    const float* b_uk  = (const float*)d_in[7];
    const float* W_uv  = (const float*)d_in[8];
    const float* b_uv  = (const float*)d_in[9];
    const float* W_uq  = (const float*)d_in[10];
    const float* b_uq  = (const float*)d_in[11];
    const float* W_qr  = (const float*)d_in[12];
    const float* b_qr  = (const float*)d_in[13];
    const float* W_kr  = (const float*)d_in[14];
    const float* b_kr  = (const float*)d_in[15];
    const float* W_fc  = (const float*)d_in[16];
    const float* b_fc  = (const float*)d_in[17];
    float* out = (float*)d_out;

    float *Xr, *cx, *kcvc, *qcqr, *Qn, *Kn, *Vt, *ao;
    float *Wx, *Wu1, *Wu2, *Wfc, *bx, *bu1, *bu2;
    cudaGetSymbolAddress((void**)&Xr,   g_Xr);
    cudaGetSymbolAddress((void**)&cx,   g_cx);
    cudaGetSymbolAddress((void**)&kcvc, g_kcvc);
    cudaGetSymbolAddress((void**)&qcqr, g_qcqr);
    cudaGetSymbolAddress((void**)&Qn,   g_Qn);
    cudaGetSymbolAddress((void**)&Kn,   g_Kn);
    cudaGetSymbolAddress((void**)&Vt,   g_Vt);
    cudaGetSymbolAddress((void**)&ao,   g_ao);
    cudaGetSymbolAddress((void**)&Wx,   g_Wx);
    cudaGetSymbolAddress((void**)&Wu1,  g_Wu1);
    cudaGetSymbolAddress((void**)&Wu2,  g_Wu2);
    cudaGetSymbolAddress((void**)&Wfc,  g_Wfc);
    cudaGetSymbolAddress((void**)&bx,   g_bx);
    cudaGetSymbolAddress((void**)&bu1,  g_bu1);
    cudaGetSymbolAddress((void**)&bu2,  g_bu2);

    // [0] weight prep + X tf32 conversion
    wprep<<<7428, dim3(32, 8)>>>(X, W_dkv, W_dq, W_kr, W_uk, W_uv, W_uq, W_qr, W_fc,
                                 b_dkv, b_dq, b_kr, b_uk, b_uv, b_uq, b_qr);

    const int GSM = 4 * BUFSZ * 4;
    cudaFuncSetAttribute(mma_gemm<true>,  cudaFuncAttributeMaxDynamicSharedMemorySize, GSM);
    cudaFuncSetAttribute(mma_gemm<false>, cudaFuncAttributeMaxDynamicSharedMemorySize, GSM);

    // [1] X projections (N=1152)
    mma_gemm<true><<<dim3(NX/128, NBS/128), 256, GSM>>>(Xr, Wx, bx, cx, NHID, NHID, NX);
    // [2] up1: kcvc = ckv @ [Wuk|Wuv] + bu1
    mma_gemm<true><<<dim3(16, NBS/128), 256, GSM>>>(cx,       Wu1, bu1, kcvc, NDOWN, NX, 2048);
    // [3] up2: qcqr = cq @ [Wuq|Wqr] + bu2
    mma_gemm<true><<<dim3(16, NBS/128), 256, GSM>>>(cx + 512, Wu2, bu2, qcqr, NDOWN, NX, 2048);

    // [4] fused pack
    pack_all<<<dim3(32, 64), 256>>>(kcvc, qcqr, cx, Qn, Kn, Vt);

    // [5] attention (ncu -s 5 target)
    const int ASM = 34304 * 4;
    cudaFuncSetAttribute(attn_mma, cudaFuncAttributeMaxDynamicSharedMemorySize, ASM);
    attn_mma<<<dim3(16, 64), 256, ASM>>>(Qn, Kn, Vt, ao);

    // [6] final projection (fp32 out)
    mma_gemm<false><<<dim3(16, NBS/128), 256, GSM>>>(ao, Wfc, b_fc, out, NUP, NUP, 2048);
}